// round 12
// baseline (speedup 1.0000x reference)
#include <cuda_runtime.h>
#include <cuda_fp16.h>
#include <math.h>
#include <stdint.h>

// ---------------- problem constants ----------------
#define NN   3
#define BB   4
#define CC   256
#define HH   40
#define WW   40
#define PP   (HH*WW)           // 1600
#define EE   6
#define NBB  (NN*BB)           // 12
#define CP   (CC*PP)           // 409600
#define BCP  (BB*CP)
#define NBCP (NN*BCP)          // 4915200

// ---------------- scratch ----------------
__device__ float g_nodes [NBCP];
__device__ float g_scores[(size_t)EE*BB*PP*PP];
__device__ float g_msg   [(size_t)EE*BCP];
__device__ float g_gates [(size_t)NBB*512*PP];
__device__ float g_cand  [NBCP];

// fp16 hi/lo split buffers (16B-aligned for cp.async)
__device__ __align__(16) __half g_atnH[(size_t)EE*BB*PP*PP];
__device__ __align__(16) __half g_atnL[(size_t)EE*BB*PP*PP];
__device__ __align__(16) __half g_nodesTH[NBCP], g_nodesTL[NBCP]; // [z][p][c]
__device__ __align__(16) __half g_thTH[NBCP],    g_thTL[NBCP];    // [z][p][c]
__device__ __align__(16) __half g_sumH[NN*BCP],  g_sumL[NN*BCP];  // [pair*b][c][q]
__device__ __align__(16) __half g_aggTH[NBCP];                    // [z][p][c] (H only)
__device__ __align__(16) __half g_rhTH[NBCP];                     // [z][p][c] (H only)
__device__ __align__(16) __half g_wgH[9*512*512], g_wgL[9*512*512]; // [s][oc][ci]
__device__ __align__(16) __half g_wcH[9*256*512], g_wcL[9*256*512];
__device__ __align__(16) __half g_wtH[CC*CC],     g_wtL[CC*CC];     // theta W [o][c]

__device__ __constant__ int c_recv[EE] = {0,0,1,1,2,2};
__device__ __constant__ int c_send[EE] = {1,2,0,2,0,1};
__device__ __constant__ int c_pair[EE] = {0,1,0,2,1,2};
__device__ __constant__ int c_p0[NN]   = {0,0,1};
__device__ __constant__ int c_p1[NN]   = {1,2,2};

// ================= low-level helpers (portable PTX only) =================
__device__ __forceinline__ uint32_t smem_u32(const void* p) {
    uint32_t a;
    asm("{ .reg .u64 t; cvta.to.shared.u64 t, %1; cvt.u32.u64 %0, t; }" : "=r"(a) : "l"(p));
    return a;
}
__device__ __forceinline__ void cp16(uint32_t dst, const void* src, bool v) {
    asm volatile("cp.async.cg.shared.global [%0], [%1], 16, %2;"
                 :: "r"(dst), "l"(src), "r"(v ? 16 : 0));
}
#define CP_COMMIT() asm volatile("cp.async.commit_group;" ::: "memory")
#define CP_WAIT1()  asm volatile("cp.async.wait_group 1;" ::: "memory")

__device__ __forceinline__ void ldsm4(uint32_t (&r)[4], uint32_t addr) {
    asm volatile("ldmatrix.sync.aligned.m8n8.x4.shared.b16 {%0,%1,%2,%3}, [%4];"
                 : "=r"(r[0]), "=r"(r[1]), "=r"(r[2]), "=r"(r[3]) : "r"(addr));
}
__device__ __forceinline__ void mma16816(float* c, const uint32_t (&a)[4],
                                         uint32_t b0, uint32_t b1) {
    asm volatile("mma.sync.aligned.m16n8k16.row.col.f32.f16.f16.f32 "
                 "{%0,%1,%2,%3}, {%4,%5,%6,%7}, {%8,%9}, {%0,%1,%2,%3};"
                 : "+f"(c[0]), "+f"(c[1]), "+f"(c[2]), "+f"(c[3])
                 : "r"(a[0]), "r"(a[1]), "r"(a[2]), "r"(a[3]), "r"(b0), "r"(b1));
}

// ---------------- tile geometry ----------------
// CTA 256 threads = 8 warps (wm 0..1 x wn 0..3); CTA tile 128x128, BK=64.
#define TSTRIDE 72
#define TILE_B  (128*TSTRIDE*2)   // 18432 bytes per tile buffer

__device__ __forceinline__ void compute_chunk(uint32_t aT, uint32_t bT,
                                              int lane, int wm, int wn,
                                              float (*acc)[4][4]) {
    const int arow = wm*64 + ((lane>>3)&1)*8 + (lane&7);
    const int acol = (lane>>4)*8;
    const int brow = wn*32 + ((lane>>4)&1)*8 + (lane&7);
    const int bcol = ((lane>>3)&1)*8;
#pragma unroll
    for (int ks = 0; ks < 4; ks++) {
        uint32_t a[4][4], b[2][4];
#pragma unroll
        for (int mt = 0; mt < 4; mt++)
            ldsm4(a[mt], aT + (uint32_t)(((arow + mt*16)*TSTRIDE) + acol + ks*16)*2);
#pragma unroll
        for (int np = 0; np < 2; np++)
            ldsm4(b[np], bT + (uint32_t)(((brow + np*16)*TSTRIDE) + bcol + ks*16)*2);
#pragma unroll
        for (int mt = 0; mt < 4; mt++)
#pragma unroll
            for (int nt = 0; nt < 4; nt++)
                mma16816(acc[mt][nt], a[mt], b[nt>>1][(nt&1)*2], b[nt>>1][(nt&1)*2+1]);
    }
}

__device__ __forceinline__ void epilogue(float (*acc)[4][4], float* out,
                                         int m0, int n0, int Mtot, int Ntot,
                                         const float* bias, int lane, int wm, int wn) {
#pragma unroll
    for (int mt = 0; mt < 4; mt++) {
        int m = m0 + wm*64 + mt*16 + (lane>>2);
        float bv0 = (bias && m < Mtot) ? bias[m] : 0.f;
        float bv1 = (bias && m+8 < Mtot) ? bias[m+8] : 0.f;
#pragma unroll
        for (int nt = 0; nt < 4; nt++) {
            int n = n0 + wn*32 + nt*8 + (lane&3)*2;
            if (n >= Ntot) continue;
            if (m < Mtot) {
                float2 v = make_float2(acc[mt][nt][0] + bv0, acc[mt][nt][1] + bv0);
                *(float2*)&out[(size_t)m*Ntot + n] = v;
            }
            if (m+8 < Mtot) {
                float2 v = make_float2(acc[mt][nt][2] + bv1, acc[mt][nt][3] + bv1);
                *(float2*)&out[(size_t)(m+8)*Ntot + n] = v;
            }
        }
    }
}

// QUAD mainloop: stage {AH, AL, BH, BL} per k0 (4 tiles), compute 3 chunks
// (AH*BH, AL*BH, AH*BL). 2 buffers, 1-deep lookahead, 2 barriers/iter.
#define MAINLOOP_QUAD(NIT)                                                        \
    stage(0, 0); CP_COMMIT();                                                     \
    for (int t = 0; t < (NIT); t++) {                                             \
        if (t+1 < (NIT)) stage(t+1, (t+1)&1);                                     \
        CP_COMMIT();                                                              \
        CP_WAIT1(); __syncthreads();                                              \
        uint32_t bo = (uint32_t)(t&1)*TILE_B;                                     \
        compute_chunk(sAh + bo, sBh + bo, lane, wm, wn, acc);                     \
        compute_chunk(sAl + bo, sBh + bo, lane, wm, wn, acc);                     \
        compute_chunk(sAh + bo, sBl + bo, lane, wm, wn, acc);                     \
        __syncthreads();                                                          \
    }

// PAIR mainloop (conv): stage {AH, AL, B}, compute 2 chunks sharing B.
#define MAINLOOP_PAIR(NIT)                                                        \
    stage(0, 0); CP_COMMIT();                                                     \
    for (int t = 0; t < (NIT); t++) {                                             \
        if (t+1 < (NIT)) stage(t+1, (t+1)&1);                                     \
        CP_COMMIT();                                                              \
        CP_WAIT1(); __syncthreads();                                              \
        uint32_t bo = (uint32_t)(t&1)*TILE_B;                                     \
        compute_chunk(sAh + bo, sB + bo, lane, wm, wn, acc);                      \
        compute_chunk(sAl + bo, sB + bo, lane, wm, wn, acc);                      \
        __syncthreads();                                                          \
    }

// ============ scores: S[p][q] = sum_c th[p][c]*nodes[q][c], quad, 4 iters ============
__global__ __launch_bounds__(256) void scores_mma() {
    __shared__ alignas(16) __half Ah[2][128][TSTRIDE];
    __shared__ alignas(16) __half Al[2][128][TSTRIDE];
    __shared__ alignas(16) __half Bh[2][128][TSTRIDE];
    __shared__ alignas(16) __half Bl[2][128][TSTRIDE];
    const int tid = threadIdx.x, lane = tid & 31, wid = tid >> 5;
    const int wm = wid & 1, wn = wid >> 1;
    const int z = blockIdx.z, e = z >> 2, b = z & 3;
    const int zr = c_recv[e]*BB + b, zs = c_send[e]*BB + b;
    const int m0 = blockIdx.y*128, n0 = blockIdx.x*128;
    float* Cp = g_scores + (size_t)z*PP*PP;
    const uint32_t sAh = smem_u32(Ah), sAl = smem_u32(Al);
    const uint32_t sBh = smem_u32(Bh), sBl = smem_u32(Bl);

    const int r0 = tid >> 2, seg8 = (tid & 3)*8;
    float acc[4][4][4] = {};

    auto stage = [&](int it, int buf) {
        int k0 = it*64;
        uint32_t aTh = sAh + buf*TILE_B, aTl = sAl + buf*TILE_B;
        uint32_t bTh = sBh + buf*TILE_B, bTl = sBl + buf*TILE_B;
#pragma unroll
        for (int i = 0; i < 2; i++) {
            int row = r0 + i*64;
            int gm = m0 + row, gn = n0 + row;
            bool va = gm < PP, vb = gn < PP;
            size_t aoff = ((size_t)zr*PP + (va ? gm : 0))*256 + k0;
            size_t boff = ((size_t)zs*PP + (vb ? gn : 0))*256 + k0;
#pragma unroll
            for (int j = 0; j < 2; j++) {
                int koff = seg8 + j*32;
                uint32_t o = (uint32_t)(row*TSTRIDE + koff)*2;
                cp16(aTh + o, g_thTH + aoff + koff, va);
                cp16(aTl + o, g_thTL + aoff + koff, va);
                cp16(bTh + o, g_nodesTH + boff + koff, vb);
                cp16(bTl + o, g_nodesTL + boff + koff, vb);
            }
        }
    };

    MAINLOOP_QUAD(4)
    epilogue(acc, Cp, m0, n0, PP, PP, nullptr, lane, wm, wn);
}

// ============ msg: M[c][p] = sum_q sum[c][q]*atn[p][q], quad, 25 iters ============
__global__ __launch_bounds__(256) void msg_mma() {
    __shared__ alignas(16) __half Ah[2][128][TSTRIDE];
    __shared__ alignas(16) __half Al[2][128][TSTRIDE];
    __shared__ alignas(16) __half Bh[2][128][TSTRIDE];
    __shared__ alignas(16) __half Bl[2][128][TSTRIDE];
    const int tid = threadIdx.x, lane = tid & 31, wid = tid >> 5;
    const int wm = wid & 1, wn = wid >> 1;
    const int z = blockIdx.z, e = z >> 2, b = z & 3;
    const int zp = c_pair[e]*BB + b;
    const int m0 = blockIdx.y*128, n0 = blockIdx.x*128;
    float* Cp = g_msg + (size_t)z*CP;
    const uint32_t sAh = smem_u32(Ah), sAl = smem_u32(Al);
    const uint32_t sBh = smem_u32(Bh), sBl = smem_u32(Bl);

    const int r0 = tid >> 2, seg8 = (tid & 3)*8;
    float acc[4][4][4] = {};

    auto stage = [&](int it, int buf) {
        int k0 = it*64;
        uint32_t aTh = sAh + buf*TILE_B, aTl = sAl + buf*TILE_B;
        uint32_t bTh = sBh + buf*TILE_B, bTl = sBl + buf*TILE_B;
#pragma unroll
        for (int i = 0; i < 2; i++) {
            int row = r0 + i*64;
            int gn = n0 + row;
            bool vb = gn < PP;
            size_t aoff = ((size_t)zp*CC + m0 + row)*PP + k0;
            size_t boff = ((size_t)z*PP + (vb ? gn : 0))*PP + k0;
#pragma unroll
            for (int j = 0; j < 2; j++) {
                int koff = seg8 + j*32;
                uint32_t o = (uint32_t)(row*TSTRIDE + koff)*2;
                cp16(aTh + o, g_sumH + aoff + koff, true);
                cp16(aTl + o, g_sumL + aoff + koff, true);
                cp16(bTh + o, g_atnH + boff + koff, vb);
                cp16(bTl + o, g_atnL + boff + koff, vb);
            }
        }
    };

    MAINLOOP_QUAD(25)
    epilogue(acc, Cp, m0, n0, CC, PP, nullptr, lane, wm, wn);
}

// ============ conv3x3 as GEMM: (wH,wL) x xH pairs, 72 pair-iters ============
__global__ __launch_bounds__(256) void conv_mma(const __half* __restrict__ wH,
                                                const __half* __restrict__ wL,
                                                const float* __restrict__ bias,
                                                const __half* __restrict__ x1H,
                                                float* __restrict__ out, int OC) {
    __shared__ alignas(16) __half Ah[2][128][TSTRIDE];
    __shared__ alignas(16) __half Al[2][128][TSTRIDE];
    __shared__ alignas(16) __half Bs[2][128][TSTRIDE];
    const int tid = threadIdx.x, lane = tid & 31, wid = tid >> 5;
    const int wm = wid & 1, wn = wid >> 1;
    const int z = blockIdx.z;
    const int m0 = blockIdx.y*128, n0 = blockIdx.x*128;
    float* pO = out + (size_t)z*OC*PP;
    const uint32_t sAh = smem_u32(Ah), sAl = smem_u32(Al), sB = smem_u32(Bs);

    const int r0 = tid >> 2, seg8 = (tid & 3)*8;
    int gn0 = n0 + r0,        y0 = gn0 / WW, x0 = gn0 % WW;
    int gn1 = n0 + r0 + 64,   y1 = gn1 / WW, x1c = gn1 % WW;
    float acc[4][4][4] = {};

    auto stage = [&](int it, int buf) {
        int kk = it*64;
        int s  = kk >> 9;
        int cw = kk & 511;               // 0,64,...,448
        int ky = s/3 - 1, kx = s%3 - 1;
        const __half* bS = (cw < 256) ? g_aggTH : x1H;
        int ci = cw & 255;
        uint32_t aTh = sAh + buf*TILE_B, aTl = sAl + buf*TILE_B, bT = sB + buf*TILE_B;
#pragma unroll
        for (int i = 0; i < 2; i++) {
            int row = r0 + i*64;
            size_t aoff = ((size_t)s*OC + m0 + row)*512 + cw;
            int yy = (i ? y1 : y0) + ky, xx = (i ? x1c : x0) + kx;
            int gnr = i ? gn1 : gn0;
            bool vb = (gnr < PP) && yy >= 0 && yy < HH && xx >= 0 && xx < WW;
            int sp = vb ? (yy*WW + xx) : 0;
            size_t boff = ((size_t)z*PP + sp)*256 + ci;
#pragma unroll
            for (int j = 0; j < 2; j++) {
                int koff = seg8 + j*32;
                uint32_t o = (uint32_t)(row*TSTRIDE + koff)*2;
                cp16(aTh + o, wH + aoff + koff, true);
                cp16(aTl + o, wL + aoff + koff, true);
                cp16(bT + o, bS + boff + koff, vb);
            }
        }
    };

    MAINLOOP_PAIR(72)
    epilogue(acc, pO, m0, n0, OC, PP, bias, lane, wm, wn);
}

// ============ theta: thT[p][o] = sum_c nodesT[p][c]*W[o][c] + b[o], quad, 4 iters ============
__global__ __launch_bounds__(256) void theta_mma(const float* __restrict__ bias) {
    __shared__ alignas(16) __half Ah[2][128][TSTRIDE];
    __shared__ alignas(16) __half Al[2][128][TSTRIDE];
    __shared__ alignas(16) __half Bh[2][128][TSTRIDE];
    __shared__ alignas(16) __half Bl[2][128][TSTRIDE];
    const int tid = threadIdx.x, lane = tid & 31, wid = tid >> 5;
    const int wm = wid & 1, wn = wid >> 1;
    const int z = blockIdx.z;
    const int m0 = blockIdx.y*128, n0 = blockIdx.x*128;
    const uint32_t sAh = smem_u32(Ah), sAl = smem_u32(Al);
    const uint32_t sBh = smem_u32(Bh), sBl = smem_u32(Bl);

    const int r0 = tid >> 2, seg8 = (tid & 3)*8;
    float acc[4][4][4] = {};

    auto stage = [&](int it, int buf) {
        int k0 = it*64;
        uint32_t aTh = sAh + buf*TILE_B, aTl = sAl + buf*TILE_B;
        uint32_t bTh = sBh + buf*TILE_B, bTl = sBl + buf*TILE_B;
#pragma unroll
        for (int i = 0; i < 2; i++) {
            int row = r0 + i*64;
            int gm = m0 + row;
            bool va = gm < PP;
            size_t aoff = ((size_t)z*PP + (va ? gm : 0))*256 + k0;
            size_t boff = (size_t)(n0 + row)*256 + k0;
#pragma unroll
            for (int j = 0; j < 2; j++) {
                int koff = seg8 + j*32;
                uint32_t o = (uint32_t)(row*TSTRIDE + koff)*2;
                cp16(aTh + o, g_nodesTH + aoff + koff, va);
                cp16(aTl + o, g_nodesTL + aoff + koff, va);
                cp16(bTh + o, g_wtH + boff + koff, true);
                cp16(bTl + o, g_wtL + boff + koff, true);
            }
        }
    };

    MAINLOOP_QUAD(4)

    // split epilogue -> thTH/thTL [z][p][c]; bias is per-COLUMN (o)
#pragma unroll
    for (int mt = 0; mt < 4; mt++) {
        int m = m0 + wm*64 + mt*16 + (lane>>2);
#pragma unroll
        for (int nt = 0; nt < 4; nt++) {
            int n = n0 + wn*32 + nt*8 + (lane&3)*2;
            float bv0 = bias[n], bv1 = bias[n+1];
#pragma unroll
            for (int half = 0; half < 2; half++) {
                int mm = m + half*8;
                if (mm >= PP) continue;
                float v0 = acc[mt][nt][half*2+0] + bv0;
                float v1 = acc[mt][nt][half*2+1] + bv1;
                __half h0 = __float2half_rn(v0);
                __half h1 = __float2half_rn(v1);
                __half l0 = __float2half_rn(v0 - __half2float(h0));
                __half l1 = __float2half_rn(v1 - __half2float(h1));
                size_t o = ((size_t)z*PP + mm)*256 + n;
                *(__half2*)&g_thTH[o] = __halves2half2(h0, h1);
                *(__half2*)&g_thTL[o] = __halves2half2(l0, l1);
            }
        }
    }
}

// ============ softmax rows -> fp16 hi/lo attention ============
__device__ __forceinline__ float block_reduce(float v, bool is_max) {
    __shared__ float s[32];
    __syncthreads();
#pragma unroll
    for (int o = 16; o > 0; o >>= 1) {
        float t = __shfl_xor_sync(0xffffffffu, v, o);
        v = is_max ? fmaxf(v, t) : (v + t);
    }
    const int w = threadIdx.x >> 5, l = threadIdx.x & 31;
    if (l == 0) s[w] = v;
    __syncthreads();
    if (w == 0) {
        v = (l < 8) ? s[l] : (is_max ? -INFINITY : 0.f);
#pragma unroll
        for (int o = 4; o > 0; o >>= 1) {
            float t = __shfl_xor_sync(0xffffffffu, v, o);
            v = is_max ? fmaxf(v, t) : (v + t);
        }
        if (l == 0) s[0] = v;
    }
    __syncthreads();
    return s[0];
}

__global__ __launch_bounds__(256) void softmax_fp() {
    const size_t row = blockIdx.x;
    const float* srow = g_scores + row*PP;
    __half* hrow = g_atnH + row*PP;
    __half* lrow = g_atnL + row*PP;
    const int t = threadIdx.x;
    float v[7];
    float mx = -INFINITY;
#pragma unroll
    for (int i = 0; i < 7; i++) {
        int idx = t + i*256;
        v[i] = (idx < PP) ? srow[idx] : -INFINITY;
        mx = fmaxf(mx, v[i]);
    }
    mx = block_reduce(mx, true);
    float sum = 0.f;
#pragma unroll
    for (int i = 0; i < 7; i++) {
        int idx = t + i*256;
        if (idx < PP) { v[i] = __expf(v[i] - mx); sum += v[i]; }
    }
    sum = block_reduce(sum, false);
    const float inv = 1.f / sum;
#pragma unroll
    for (int i = 0; i < 7; i++) {
        int idx = t + i*256;
        if (idx < PP) {
            float a = v[i] * inv;
            __half h = __float2half_rn(a);
            __half l = __float2half_rn(a - __half2float(h));
            hrow[idx] = h; lrow[idx] = l;
        }
    }
}

// ============ split / transpose prep kernels ============
__device__ __forceinline__ void hsplit(float v, __half* h, __half* l) {
    __half hh = __float2half_rn(v);
    *h = hh;
    *l = __float2half_rn(v - __half2float(hh));
}

__global__ __launch_bounds__(256) void tsplit(const float* __restrict__ src,
                                              __half* __restrict__ dh,
                                              __half* __restrict__ dl) {
    __shared__ float tile[32][33];
    const int z = blockIdx.z, p0 = blockIdx.x*32, c0 = blockIdx.y*32;
    const int tx = threadIdx.x, ty = threadIdx.y;
    const float* s = src + (size_t)z*CP;
#pragma unroll
    for (int k = 0; k < 4; k++)
        tile[ty + 8*k][tx] = s[(size_t)(c0 + ty + 8*k)*PP + p0 + tx];
    __syncthreads();
#pragma unroll
    for (int k = 0; k < 4; k++) {
        float v = tile[tx][ty + 8*k];
        size_t o = ((size_t)z*PP + p0 + ty + 8*k)*256 + c0 + tx;
        hsplit(v, &dh[o], &dl[o]);
    }
}

// aggT (H only): agg = msg[e=2n]+msg[e=2n+1], -> [z][p][c]; msg layout [e*BB+b][c][p]
__global__ __launch_bounds__(256) void aggT_t() {
    __shared__ float tile[32][33];
    const int z = blockIdx.z, p0 = blockIdx.x*32, c0 = blockIdx.y*32;
    const int n = z >> 2, b = z & 3;
    const int tx = threadIdx.x, ty = threadIdx.y;
    const float* m1 = g_msg + (size_t)(8*n + b)*CP;
    const float* m2 = g_msg + (size_t)(8*n + 4 + b)*CP;
#pragma unroll
    for (int k = 0; k < 4; k++) {
        size_t o = (size_t)(c0 + ty + 8*k)*PP + p0 + tx;
        tile[ty + 8*k][tx] = m1[o] + m2[o];
    }
    __syncthreads();
#pragma unroll
    for (int k = 0; k < 4; k++) {
        size_t o = ((size_t)z*PP + p0 + ty + 8*k)*256 + c0 + tx;
        g_aggTH[o] = __float2half_rn(tile[tx][ty + 8*k]);
    }
}

// rhT (H only): rh = sigmoid(gates_r) * h -> [z][p][c]
__global__ __launch_bounds__(256) void rhT_t() {
    __shared__ float tile[32][33];
    const int z = blockIdx.z, p0 = blockIdx.x*32, c0 = blockIdx.y*32;
    const int tx = threadIdx.x, ty = threadIdx.y;
    const float* gp = g_gates + (size_t)z*512*PP;
    const float* hp = g_nodes + (size_t)z*CP;
#pragma unroll
    for (int k = 0; k < 4; k++) {
        size_t o = (size_t)(c0 + ty + 8*k)*PP + p0 + tx;
        float g = gp[o];
        float r = 1.f / (1.f + __expf(-g));
        tile[ty + 8*k][tx] = r * hp[o];
    }
    __syncthreads();
#pragma unroll
    for (int k = 0; k < 4; k++) {
        size_t o = ((size_t)z*PP + p0 + ty + 8*k)*256 + c0 + tx;
        g_rhTH[o] = __float2half_rn(tile[tx][ty + 8*k]);
    }
}

__global__ __launch_bounds__(256) void sum_split() {
    size_t i = (size_t)blockIdx.x*256 + threadIdx.x;
    if (i >= (size_t)NN*BCP) return;
    int z2 = (int)(i / CP); size_t cp = i % CP;
    int pr = z2 >> 2, b = z2 & 3;
    float v = g_nodes[(size_t)(c_p0[pr]*BB + b)*CP + cp] +
              g_nodes[(size_t)(c_p1[pr]*BB + b)*CP + cp];
    hsplit(v, &g_sumH[i], &g_sumL[i]);
}

__global__ __launch_bounds__(256) void update_kernel() {
    size_t i = (size_t)blockIdx.x*256 + threadIdx.x;
    if (i >= (size_t)NBCP) return;
    size_t nb = i / CP, cp = i % CP;
    float gz = g_gates[nb*(size_t)(512*PP) + (size_t)CC*PP + cp];
    float zv = 1.f / (1.f + __expf(-gz));
    float h = g_nodes[i];
    float cd = tanhf(g_cand[i]);
    g_nodes[i] = (1.f - zv)*h + zv*cd;
}

__global__ __launch_bounds__(256) void wsplit(const float* __restrict__ w,
                                              __half* __restrict__ dh,
                                              __half* __restrict__ dl, int OC) {
    size_t i = (size_t)blockIdx.x*256 + threadIdx.x;
    size_t total = (size_t)9*OC*512;
    if (i >= total) return;
    int ci = (int)(i & 511);
    int oc = (int)((i >> 9) % OC);
    int s  = (int)(i / ((size_t)OC*512));
    float v = w[((size_t)oc*512 + ci)*9 + s];
    hsplit(v, &dh[i], &dl[i]);
}

__global__ __launch_bounds__(256) void wtheta_split(const float* __restrict__ w) {
    int i = blockIdx.x*256 + threadIdx.x;
    if (i >= CC*CC) return;
    hsplit(w[i], &g_wtH[i], &g_wtL[i]);
}

__global__ __launch_bounds__(256) void copy_in(const float* __restrict__ src) {
    size_t i = (size_t)blockIdx.x*256 + threadIdx.x;
    if (i < (size_t)NBCP/4) ((float4*)g_nodes)[i] = ((const float4*)src)[i];
}
__global__ __launch_bounds__(256) void copy_out(float* __restrict__ dst) {
    size_t i = (size_t)blockIdx.x*256 + threadIdx.x;
    if (i < (size_t)NBCP/4) ((float4*)dst)[i] = ((const float4*)g_nodes)[i];
}

// ---------------- host launch ----------------
extern "C" void kernel_launch(void* const* d_in, const int* in_sizes, int n_in,
                              void* d_out, int out_size) {
    const float* in_nodes = (const float*)d_in[0];
    const float* theta_w  = (const float*)d_in[1];
    const float* theta_b  = (const float*)d_in[2];
    const float* gw       = (const float*)d_in[3];
    const float* gb       = (const float*)d_in[4];
    const float* cw       = (const float*)d_in[5];
    const float* cb       = (const float*)d_in[6];
    float* out = (float*)d_out;

    __half *p_wgH, *p_wgL, *p_wcH, *p_wcL, *p_nTH, *p_nTL, *p_rhH;
    float *p_nodes, *p_gates, *p_cand;
    cudaGetSymbolAddress((void**)&p_wgH, g_wgH);
    cudaGetSymbolAddress((void**)&p_wgL, g_wgL);
    cudaGetSymbolAddress((void**)&p_wcH, g_wcH);
    cudaGetSymbolAddress((void**)&p_wcL, g_wcL);
    cudaGetSymbolAddress((void**)&p_nTH, g_nodesTH);
    cudaGetSymbolAddress((void**)&p_nTL, g_nodesTL);
    cudaGetSymbolAddress((void**)&p_rhH, g_rhTH);
    cudaGetSymbolAddress((void**)&p_nodes, g_nodes);
    cudaGetSymbolAddress((void**)&p_gates, g_gates);
    cudaGetSymbolAddress((void**)&p_cand,  g_cand);

    copy_in<<<(NBCP/4 + 255)/256, 256>>>(in_nodes);
    wsplit<<<((size_t)9*512*512 + 255)/256, 256>>>(gw, p_wgH, p_wgL, 512);
    wsplit<<<((size_t)9*256*512 + 255)/256, 256>>>(cw, p_wcH, p_wcL, 256);
    wtheta_split<<<(CC*CC + 255)/256, 256>>>(theta_w);

    const int EW = NBCP/256;  // 19200
    const dim3 tgrid(50, 8, 12), tblk(32, 8);
    for (int pass = 0; pass < 2; pass++) {
        tsplit<<<tgrid, tblk>>>(p_nodes, p_nTH, p_nTL);
        theta_mma<<<dim3(2, 13, NBB), 256>>>(theta_b);
        sum_split<<<EW, 256>>>();
        scores_mma<<<dim3(13, 13, EE*BB), 256>>>();
        softmax_fp<<<EE*BB*PP, 256>>>();
        msg_mma<<<dim3(13, 2, EE*BB), 256>>>();
        aggT_t<<<tgrid, tblk>>>();
        conv_mma<<<dim3(13, 4, NBB), 256>>>(p_wgH, p_wgL, gb, p_nTH, p_gates, 512);
        rhT_t<<<tgrid, tblk>>>();
        conv_mma<<<dim3(13, 2, NBB), 256>>>(p_wcH, p_wcL, cb, p_rhH, p_cand, 256);
        update_kernel<<<EW, 256>>>();
    }
    copy_out<<<(NBCP/4 + 255)/256, 256>>>(out);
}

// round 13
// speedup vs baseline: 1.1123x; 1.1123x over previous
#include <cuda_runtime.h>
#include <cuda_fp16.h>
#include <math.h>
#include <stdint.h>

// ---------------- problem constants ----------------
#define NN   3
#define BB   4
#define CC   256
#define HH   40
#define WW   40
#define PP   (HH*WW)           // 1600
#define EE   6
#define NBB  (NN*BB)           // 12
#define CP   (CC*PP)           // 409600
#define BCP  (BB*CP)
#define NBCP (NN*BCP)          // 4915200

// ---------------- scratch ----------------
__device__ float g_nodes [NBCP];
__device__ float g_scores[(size_t)EE*BB*PP*PP];
__device__ float g_msg   [(size_t)EE*BCP];
__device__ float g_gates [(size_t)NBB*512*PP];
__device__ float g_cand  [NBCP];

// fp16 hi/lo split buffers (16B-aligned for cp.async)
__device__ __align__(16) __half g_atnH[(size_t)EE*BB*PP*PP];      // atn hi only (2-seg msg)
__device__ __align__(16) __half g_nodesTH[NBCP], g_nodesTL[NBCP]; // [z][p][c]
__device__ __align__(16) __half g_thTH[NBCP],    g_thTL[NBCP];    // [z][p][c]
__device__ __align__(16) __half g_sumH[NN*BCP],  g_sumL[NN*BCP];  // [pair*b][c][q]
__device__ __align__(16) __half g_aggTH[NBCP];                    // [z][p][c] (H only)
__device__ __align__(16) __half g_rhTH[NBCP];                     // [z][p][c] (H only)
__device__ __align__(16) __half g_wgH[9*512*512], g_wgL[9*512*512]; // [s][oc][ci]
__device__ __align__(16) __half g_wcH[9*256*512], g_wcL[9*256*512];
__device__ __align__(16) __half g_wtH[CC*CC],     g_wtL[CC*CC];     // theta W [o][c]

__device__ __constant__ int c_recv[EE] = {0,0,1,1,2,2};
__device__ __constant__ int c_send[EE] = {1,2,0,2,0,1};
__device__ __constant__ int c_pair[EE] = {0,1,0,2,1,2};
__device__ __constant__ int c_p0[NN]   = {0,0,1};
__device__ __constant__ int c_p1[NN]   = {1,2,2};

// ================= low-level helpers (portable PTX only) =================
__device__ __forceinline__ uint32_t smem_u32(const void* p) {
    uint32_t a;
    asm("{ .reg .u64 t; cvta.to.shared.u64 t, %1; cvt.u32.u64 %0, t; }" : "=r"(a) : "l"(p));
    return a;
}
__device__ __forceinline__ void cp16(uint32_t dst, const void* src, bool v) {
    asm volatile("cp.async.cg.shared.global [%0], [%1], 16, %2;"
                 :: "r"(dst), "l"(src), "r"(v ? 16 : 0));
}
#define CP_COMMIT() asm volatile("cp.async.commit_group;" ::: "memory")
#define CP_WAIT1()  asm volatile("cp.async.wait_group 1;" ::: "memory")

__device__ __forceinline__ void ldsm4(uint32_t (&r)[4], uint32_t addr) {
    asm volatile("ldmatrix.sync.aligned.m8n8.x4.shared.b16 {%0,%1,%2,%3}, [%4];"
                 : "=r"(r[0]), "=r"(r[1]), "=r"(r[2]), "=r"(r[3]) : "r"(addr));
}
__device__ __forceinline__ void mma16816(float* c, const uint32_t (&a)[4],
                                         uint32_t b0, uint32_t b1) {
    asm volatile("mma.sync.aligned.m16n8k16.row.col.f32.f16.f16.f32 "
                 "{%0,%1,%2,%3}, {%4,%5,%6,%7}, {%8,%9}, {%0,%1,%2,%3};"
                 : "+f"(c[0]), "+f"(c[1]), "+f"(c[2]), "+f"(c[3])
                 : "r"(a[0]), "r"(a[1]), "r"(a[2]), "r"(a[3]), "r"(b0), "r"(b1));
}

// ---------------- tile geometry ----------------
// CTA 256 threads = 8 warps (wm 0..1 x wn 0..3); CTA tile 128x128, BK=64.
// PAIR iterations: stage {A_hi, A_lo, B} (3 tiles), compute 2 chunks sharing B.
#define TSTRIDE 72
#define TILE_B  (128*TSTRIDE*2)   // 18432 bytes per tile buffer

__device__ __forceinline__ void compute_chunk(uint32_t aT, uint32_t bT,
                                              int lane, int wm, int wn,
                                              float (*acc)[4][4]) {
    const int arow = wm*64 + ((lane>>3)&1)*8 + (lane&7);
    const int acol = (lane>>4)*8;
    const int brow = wn*32 + ((lane>>4)&1)*8 + (lane&7);
    const int bcol = ((lane>>3)&1)*8;
#pragma unroll
    for (int ks = 0; ks < 4; ks++) {
        uint32_t a[4][4], b[2][4];
#pragma unroll
        for (int mt = 0; mt < 4; mt++)
            ldsm4(a[mt], aT + (uint32_t)(((arow + mt*16)*TSTRIDE) + acol + ks*16)*2);
#pragma unroll
        for (int np = 0; np < 2; np++)
            ldsm4(b[np], bT + (uint32_t)(((brow + np*16)*TSTRIDE) + bcol + ks*16)*2);
#pragma unroll
        for (int mt = 0; mt < 4; mt++)
#pragma unroll
            for (int nt = 0; nt < 4; nt++)
                mma16816(acc[mt][nt], a[mt], b[nt>>1][(nt&1)*2], b[nt>>1][(nt&1)*2+1]);
    }
}

__device__ __forceinline__ void epilogue(float (*acc)[4][4], float* out,
                                         int m0, int n0, int Mtot, int Ntot,
                                         const float* bias, int lane, int wm, int wn) {
#pragma unroll
    for (int mt = 0; mt < 4; mt++) {
        int m = m0 + wm*64 + mt*16 + (lane>>2);
        float bv0 = (bias && m < Mtot) ? bias[m] : 0.f;
        float bv1 = (bias && m+8 < Mtot) ? bias[m+8] : 0.f;
#pragma unroll
        for (int nt = 0; nt < 4; nt++) {
            int n = n0 + wn*32 + nt*8 + (lane&3)*2;
            if (n >= Ntot) continue;
            if (m < Mtot) {
                float2 v = make_float2(acc[mt][nt][0] + bv0, acc[mt][nt][1] + bv0);
                *(float2*)&out[(size_t)m*Ntot + n] = v;
            }
            if (m+8 < Mtot) {
                float2 v = make_float2(acc[mt][nt][2] + bv1, acc[mt][nt][3] + bv1);
                *(float2*)&out[(size_t)(m+8)*Ntot + n] = v;
            }
        }
    }
}

// Pair-iteration mainloop: 2 buffers, 1-deep lookahead (R11 structure).
#define MAINLOOP(NIT, ISPAIR)                                                     \
    stage(0, 0); CP_COMMIT();                                                     \
    for (int t = 0; t < (NIT); t++) {                                             \
        if (t+1 < (NIT)) stage(t+1, (t+1)&1);                                     \
        CP_COMMIT();                                                              \
        CP_WAIT1(); __syncthreads();                                              \
        uint32_t bufo = (uint32_t)(t&1)*TILE_B;                                   \
        compute_chunk(sAh + bufo, sB + bufo, lane, wm, wn, acc);                  \
        if (ISPAIR) compute_chunk(sAl + bufo, sB + bufo, lane, wm, wn, acc);      \
        __syncthreads();                                                          \
    }

// ============ scores: S[p][q] = sum_c th[p][c]*nodes[q][c], 3-seg paired ============
// iters 0..3: pair (thH,thL)xnH @ k0=it*64 ; iters 4..7: single thH x nL @ (it-4)*64
__global__ __launch_bounds__(256) void scores_mma() {
    __shared__ alignas(16) __half Ah[2][128][TSTRIDE];
    __shared__ alignas(16) __half Al[2][128][TSTRIDE];
    __shared__ alignas(16) __half Bs[2][128][TSTRIDE];
    const int tid = threadIdx.x, lane = tid & 31, wid = tid >> 5;
    const int wm = wid & 1, wn = wid >> 1;
    const int z = blockIdx.z, e = z >> 2, b = z & 3;
    const int zr = c_recv[e]*BB + b, zs = c_send[e]*BB + b;
    const int m0 = blockIdx.y*128, n0 = blockIdx.x*128;
    float* Cp = g_scores + (size_t)z*PP*PP;
    const uint32_t sAh = smem_u32(Ah), sAl = smem_u32(Al), sB = smem_u32(Bs);

    const int r0 = tid >> 2, seg8 = (tid & 3)*8;
    float acc[4][4][4] = {};

    auto stage = [&](int it, int buf) {
        bool pair = it < 4;
        int k0 = (pair ? it : it - 4)*64;
        const __half* bS = pair ? g_nodesTH : g_nodesTL;
        uint32_t aTh = sAh + buf*TILE_B, aTl = sAl + buf*TILE_B, bT = sB + buf*TILE_B;
#pragma unroll
        for (int i = 0; i < 2; i++) {
            int row = r0 + i*64;
            int gm = m0 + row, gn = n0 + row;
            bool va = gm < PP, vb = gn < PP;
            size_t aoff = ((size_t)zr*PP + (va ? gm : 0))*256 + k0;
            size_t boff = ((size_t)zs*PP + (vb ? gn : 0))*256 + k0;
#pragma unroll
            for (int j = 0; j < 2; j++) {
                int koff = seg8 + j*32;
                uint32_t o = (uint32_t)(row*TSTRIDE + koff)*2;
                cp16(aTh + o, g_thTH + aoff + koff, va);
                if (pair) cp16(aTl + o, g_thTL + aoff + koff, va);
                cp16(bT + o, bS + boff + koff, vb);
            }
        }
    };

    MAINLOOP(8, (t < 4))
    epilogue(acc, Cp, m0, n0, PP, PP, nullptr, lane, wm, wn);
}

// ============ msg: M[c][p] = sum_q sum[c][q]*atn[p][q], 2-seg paired ============
// 25 pair iterations: (sumH,sumL) x atnH @ k0=it*64. (atnL term dropped: ~2^-12 rel)
__global__ __launch_bounds__(256) void msg_mma() {
    __shared__ alignas(16) __half Ah[2][128][TSTRIDE];
    __shared__ alignas(16) __half Al[2][128][TSTRIDE];
    __shared__ alignas(16) __half Bs[2][128][TSTRIDE];
    const int tid = threadIdx.x, lane = tid & 31, wid = tid >> 5;
    const int wm = wid & 1, wn = wid >> 1;
    const int z = blockIdx.z, e = z >> 2, b = z & 3;
    const int zp = c_pair[e]*BB + b;
    const int m0 = blockIdx.y*128, n0 = blockIdx.x*128;
    float* Cp = g_msg + (size_t)z*CP;
    const uint32_t sAh = smem_u32(Ah), sAl = smem_u32(Al), sB = smem_u32(Bs);

    const int r0 = tid >> 2, seg8 = (tid & 3)*8;
    float acc[4][4][4] = {};

    auto stage = [&](int it, int buf) {
        int k0 = it*64;
        uint32_t aTh = sAh + buf*TILE_B, aTl = sAl + buf*TILE_B, bT = sB + buf*TILE_B;
#pragma unroll
        for (int i = 0; i < 2; i++) {
            int row = r0 + i*64;
            int gn = n0 + row;
            bool vb = gn < PP;
            size_t aoff = ((size_t)zp*CC + m0 + row)*PP + k0;
            size_t boff = ((size_t)z*PP + (vb ? gn : 0))*PP + k0;
#pragma unroll
            for (int j = 0; j < 2; j++) {
                int koff = seg8 + j*32;
                uint32_t o = (uint32_t)(row*TSTRIDE + koff)*2;
                cp16(aTh + o, g_sumH + aoff + koff, true);
                cp16(aTl + o, g_sumL + aoff + koff, true);
                cp16(bT + o, g_atnH + boff + koff, vb);
            }
        }
    };

    MAINLOOP(25, true)
    epilogue(acc, Cp, m0, n0, CC, PP, nullptr, lane, wm, wn);
}

// ============ conv3x3 as GEMM: (wH,wL) x xH pairs, 72 pair-iters ============
__global__ __launch_bounds__(256) void conv_mma(const __half* __restrict__ wH,
                                                const __half* __restrict__ wL,
                                                const float* __restrict__ bias,
                                                const __half* __restrict__ x1H,
                                                float* __restrict__ out, int OC) {
    __shared__ alignas(16) __half Ah[2][128][TSTRIDE];
    __shared__ alignas(16) __half Al[2][128][TSTRIDE];
    __shared__ alignas(16) __half Bs[2][128][TSTRIDE];
    const int tid = threadIdx.x, lane = tid & 31, wid = tid >> 5;
    const int wm = wid & 1, wn = wid >> 1;
    const int z = blockIdx.z;
    const int m0 = blockIdx.y*128, n0 = blockIdx.x*128;
    float* pO = out + (size_t)z*OC*PP;
    const uint32_t sAh = smem_u32(Ah), sAl = smem_u32(Al), sB = smem_u32(Bs);

    const int r0 = tid >> 2, seg8 = (tid & 3)*8;
    int gn0 = n0 + r0,        y0 = gn0 / WW, x0 = gn0 % WW;
    int gn1 = n0 + r0 + 64,   y1 = gn1 / WW, x1c = gn1 % WW;
    float acc[4][4][4] = {};

    auto stage = [&](int it, int buf) {
        int kk = it*64;
        int s  = kk >> 9;
        int cw = kk & 511;               // 0,64,...,448
        int ky = s/3 - 1, kx = s%3 - 1;
        const __half* bS = (cw < 256) ? g_aggTH : x1H;
        int ci = cw & 255;
        uint32_t aTh = sAh + buf*TILE_B, aTl = sAl + buf*TILE_B, bT = sB + buf*TILE_B;
#pragma unroll
        for (int i = 0; i < 2; i++) {
            int row = r0 + i*64;
            size_t aoff = ((size_t)s*OC + m0 + row)*512 + cw;
            int yy = (i ? y1 : y0) + ky, xx = (i ? x1c : x0) + kx;
            int gnr = i ? gn1 : gn0;
            bool vb = (gnr < PP) && yy >= 0 && yy < HH && xx >= 0 && xx < WW;
            int sp = vb ? (yy*WW + xx) : 0;
            size_t boff = ((size_t)z*PP + sp)*256 + ci;
#pragma unroll
            for (int j = 0; j < 2; j++) {
                int koff = seg8 + j*32;
                uint32_t o = (uint32_t)(row*TSTRIDE + koff)*2;
                cp16(aTh + o, wH + aoff + koff, true);
                cp16(aTl + o, wL + aoff + koff, true);
                cp16(bT + o, bS + boff + koff, vb);
            }
        }
    };

    MAINLOOP(72, true)
    epilogue(acc, pO, m0, n0, OC, PP, bias, lane, wm, wn);
}

// ============ theta: thT[p][o] = sum_c nodesT[p][c]*W[o][c] + b[o], 3-seg paired ============
__global__ __launch_bounds__(256) void theta_mma(const float* __restrict__ bias) {
    __shared__ alignas(16) __half Ah[2][128][TSTRIDE];
    __shared__ alignas(16) __half Al[2][128][TSTRIDE];
    __shared__ alignas(16) __half Bs[2][128][TSTRIDE];
    const int tid = threadIdx.x, lane = tid & 31, wid = tid >> 5;
    const int wm = wid & 1, wn = wid >> 1;
    const int z = blockIdx.z;
    const int m0 = blockIdx.y*128, n0 = blockIdx.x*128;
    const uint32_t sAh = smem_u32(Ah), sAl = smem_u32(Al), sB = smem_u32(Bs);

    const int r0 = tid >> 2, seg8 = (tid & 3)*8;
    float acc[4][4][4] = {};

    auto stage = [&](int it, int buf) {
        bool pair = it < 4;
        int k0 = (it & 3)*64;
        const __half* bS = pair ? g_wtH : g_wtL;
        uint32_t aTh = sAh + buf*TILE_B, aTl = sAl + buf*TILE_B, bT = sB + buf*TILE_B;
#pragma unroll
        for (int i = 0; i < 2; i++) {
            int row = r0 + i*64;
            int gm = m0 + row;
            bool va = gm < PP;
            size_t aoff = ((size_t)z*PP + (va ? gm : 0))*256 + k0;
            size_t boff = (size_t)(n0 + row)*256 + k0;
#pragma unroll
            for (int j = 0; j < 2; j++) {
                int koff = seg8 + j*32;
                uint32_t o = (uint32_t)(row*TSTRIDE + koff)*2;
                cp16(aTh + o, g_nodesTH + aoff + koff, va);
                if (pair) cp16(aTl + o, g_nodesTL + aoff + koff, va);
                cp16(bT + o, bS + boff + koff, true);
            }
        }
    };

    MAINLOOP(8, (t < 4))

    // split epilogue -> thTH/thTL [z][p][c]; bias is per-COLUMN (o)
#pragma unroll
    for (int mt = 0; mt < 4; mt++) {
        int m = m0 + wm*64 + mt*16 + (lane>>2);
#pragma unroll
        for (int nt = 0; nt < 4; nt++) {
            int n = n0 + wn*32 + nt*8 + (lane&3)*2;
            float bv0 = bias[n], bv1 = bias[n+1];
#pragma unroll
            for (int half = 0; half < 2; half++) {
                int mm = m + half*8;
                if (mm >= PP) continue;
                float v0 = acc[mt][nt][half*2+0] + bv0;
                float v1 = acc[mt][nt][half*2+1] + bv1;
                __half h0 = __float2half_rn(v0);
                __half h1 = __float2half_rn(v1);
                __half l0 = __float2half_rn(v0 - __half2float(h0));
                __half l1 = __float2half_rn(v1 - __half2float(h1));
                size_t o = ((size_t)z*PP + mm)*256 + n;
                *(__half2*)&g_thTH[o] = __halves2half2(h0, h1);
                *(__half2*)&g_thTL[o] = __halves2half2(l0, l1);
            }
        }
    }
}

// ============ softmax rows -> fp16 attention (hi only) ============
__device__ __forceinline__ float block_reduce(float v, bool is_max) {
    __shared__ float s[32];
    __syncthreads();
#pragma unroll
    for (int o = 16; o > 0; o >>= 1) {
        float t = __shfl_xor_sync(0xffffffffu, v, o);
        v = is_max ? fmaxf(v, t) : (v + t);
    }
    const int w = threadIdx.x >> 5, l = threadIdx.x & 31;
    if (l == 0) s[w] = v;
    __syncthreads();
    if (w == 0) {
        v = (l < 8) ? s[l] : (is_max ? -INFINITY : 0.f);
#pragma unroll
        for (int o = 4; o > 0; o >>= 1) {
            float t = __shfl_xor_sync(0xffffffffu, v, o);
            v = is_max ? fmaxf(v, t) : (v + t);
        }
        if (l == 0) s[0] = v;
    }
    __syncthreads();
    return s[0];
}

__global__ __launch_bounds__(256) void softmax_fp() {
    const size_t row = blockIdx.x;
    const float* srow = g_scores + row*PP;
    __half* hrow = g_atnH + row*PP;
    const int t = threadIdx.x;
    float v[7];
    float mx = -INFINITY;
#pragma unroll
    for (int i = 0; i < 7; i++) {
        int idx = t + i*256;
        v[i] = (idx < PP) ? srow[idx] : -INFINITY;
        mx = fmaxf(mx, v[i]);
    }
    mx = block_reduce(mx, true);
    float sum = 0.f;
#pragma unroll
    for (int i = 0; i < 7; i++) {
        int idx = t + i*256;
        if (idx < PP) { v[i] = __expf(v[i] - mx); sum += v[i]; }
    }
    sum = block_reduce(sum, false);
    const float inv = 1.f / sum;
#pragma unroll
    for (int i = 0; i < 7; i++) {
        int idx = t + i*256;
        if (idx < PP) hrow[idx] = __float2half_rn(v[i] * inv);
    }
}

// ============ split / transpose prep kernels ============
__device__ __forceinline__ void hsplit(float v, __half* h, __half* l) {
    __half hh = __float2half_rn(v);
    *h = hh;
    *l = __float2half_rn(v - __half2float(hh));
}

__global__ __launch_bounds__(256) void tsplit(const float* __restrict__ src,
                                              __half* __restrict__ dh,
                                              __half* __restrict__ dl) {
    __shared__ float tile[32][33];
    const int z = blockIdx.z, p0 = blockIdx.x*32, c0 = blockIdx.y*32;
    const int tx = threadIdx.x, ty = threadIdx.y;
    const float* s = src + (size_t)z*CP;
#pragma unroll
    for (int k = 0; k < 4; k++)
        tile[ty + 8*k][tx] = s[(size_t)(c0 + ty + 8*k)*PP + p0 + tx];
    __syncthreads();
#pragma unroll
    for (int k = 0; k < 4; k++) {
        float v = tile[tx][ty + 8*k];
        size_t o = ((size_t)z*PP + p0 + ty + 8*k)*256 + c0 + tx;
        hsplit(v, &dh[o], &dl[o]);
    }
}

// aggT (H only): agg = msg[e=2n]+msg[e=2n+1], -> [z][p][c]; msg layout [e*BB+b][c][p]
__global__ __launch_bounds__(256) void aggT_t() {
    __shared__ float tile[32][33];
    const int z = blockIdx.z, p0 = blockIdx.x*32, c0 = blockIdx.y*32;
    const int n = z >> 2, b = z & 3;
    const int tx = threadIdx.x, ty = threadIdx.y;
    const float* m1 = g_msg + (size_t)(8*n + b)*CP;
    const float* m2 = g_msg + (size_t)(8*n + 4 + b)*CP;
#pragma unroll
    for (int k = 0; k < 4; k++) {
        size_t o = (size_t)(c0 + ty + 8*k)*PP + p0 + tx;
        tile[ty + 8*k][tx] = m1[o] + m2[o];
    }
    __syncthreads();
#pragma unroll
    for (int k = 0; k < 4; k++) {
        size_t o = ((size_t)z*PP + p0 + ty + 8*k)*256 + c0 + tx;
        g_aggTH[o] = __float2half_rn(tile[tx][ty + 8*k]);
    }
}

// rhT (H only): rh = sigmoid(gates_r) * h -> [z][p][c]
__global__ __launch_bounds__(256) void rhT_t() {
    __shared__ float tile[32][33];
    const int z = blockIdx.z, p0 = blockIdx.x*32, c0 = blockIdx.y*32;
    const int tx = threadIdx.x, ty = threadIdx.y;
    const float* gp = g_gates + (size_t)z*512*PP;
    const float* hp = g_nodes + (size_t)z*CP;
#pragma unroll
    for (int k = 0; k < 4; k++) {
        size_t o = (size_t)(c0 + ty + 8*k)*PP + p0 + tx;
        float g = gp[o];
        float r = 1.f / (1.f + __expf(-g));
        tile[ty + 8*k][tx] = r * hp[o];
    }
    __syncthreads();
#pragma unroll
    for (int k = 0; k < 4; k++) {
        size_t o = ((size_t)z*PP + p0 + ty + 8*k)*256 + c0 + tx;
        g_rhTH[o] = __float2half_rn(tile[tx][ty + 8*k]);
    }
}

__global__ __launch_bounds__(256) void sum_split() {
    size_t i = (size_t)blockIdx.x*256 + threadIdx.x;
    if (i >= (size_t)NN*BCP) return;
    int z2 = (int)(i / CP); size_t cp = i % CP;
    int pr = z2 >> 2, b = z2 & 3;
    float v = g_nodes[(size_t)(c_p0[pr]*BB + b)*CP + cp] +
              g_nodes[(size_t)(c_p1[pr]*BB + b)*CP + cp];
    hsplit(v, &g_sumH[i], &g_sumL[i]);
}

__global__ __launch_bounds__(256) void update_kernel() {
    size_t i = (size_t)blockIdx.x*256 + threadIdx.x;
    if (i >= (size_t)NBCP) return;
    size_t nb = i / CP, cp = i % CP;
    float gz = g_gates[nb*(size_t)(512*PP) + (size_t)CC*PP + cp];
    float zv = 1.f / (1.f + __expf(-gz));
    float h = g_nodes[i];
    float cd = tanhf(g_cand[i]);
    g_nodes[i] = (1.f - zv)*h + zv*cd;
}

__global__ __launch_bounds__(256) void wsplit(const float* __restrict__ w,
                                              __half* __restrict__ dh,
                                              __half* __restrict__ dl, int OC) {
    size_t i = (size_t)blockIdx.x*256 + threadIdx.x;
    size_t total = (size_t)9*OC*512;
    if (i >= total) return;
    int ci = (int)(i & 511);
    int oc = (int)((i >> 9) % OC);
    int s  = (int)(i / ((size_t)OC*512));
    float v = w[((size_t)oc*512 + ci)*9 + s];
    hsplit(v, &dh[i], &dl[i]);
}

__global__ __launch_bounds__(256) void wtheta_split(const float* __restrict__ w) {
    int i = blockIdx.x*256 + threadIdx.x;
    if (i >= CC*CC) return;
    hsplit(w[i], &g_wtH[i], &g_wtL[i]);
}

__global__ __launch_bounds__(256) void copy_in(const float* __restrict__ src) {
    size_t i = (size_t)blockIdx.x*256 + threadIdx.x;
    if (i < (size_t)NBCP/4) ((float4*)g_nodes)[i] = ((const float4*)src)[i];
}
__global__ __launch_bounds__(256) void copy_out(float* __restrict__ dst) {
    size_t i = (size_t)blockIdx.x*256 + threadIdx.x;
    if (i < (size_t)NBCP/4) ((float4*)dst)[i] = ((const float4*)g_nodes)[i];
}

// ---------------- host launch ----------------
extern "C" void kernel_launch(void* const* d_in, const int* in_sizes, int n_in,
                              void* d_out, int out_size) {
    const float* in_nodes = (const float*)d_in[0];
    const float* theta_w  = (const float*)d_in[1];
    const float* theta_b  = (const float*)d_in[2];
    const float* gw       = (const float*)d_in[3];
    const float* gb       = (const float*)d_in[4];
    const float* cw       = (const float*)d_in[5];
    const float* cb       = (const float*)d_in[6];
    float* out = (float*)d_out;

    __half *p_wgH, *p_wgL, *p_wcH, *p_wcL, *p_nTH, *p_nTL, *p_rhH;
    float *p_nodes, *p_gates, *p_cand;
    cudaGetSymbolAddress((void**)&p_wgH, g_wgH);
    cudaGetSymbolAddress((void**)&p_wgL, g_wgL);
    cudaGetSymbolAddress((void**)&p_wcH, g_wcH);
    cudaGetSymbolAddress((void**)&p_wcL, g_wcL);
    cudaGetSymbolAddress((void**)&p_nTH, g_nodesTH);
    cudaGetSymbolAddress((void**)&p_nTL, g_nodesTL);
    cudaGetSymbolAddress((void**)&p_rhH, g_rhTH);
    cudaGetSymbolAddress((void**)&p_nodes, g_nodes);
    cudaGetSymbolAddress((void**)&p_gates, g_gates);
    cudaGetSymbolAddress((void**)&p_cand,  g_cand);

    copy_in<<<(NBCP/4 + 255)/256, 256>>>(in_nodes);
    wsplit<<<((size_t)9*512*512 + 255)/256, 256>>>(gw, p_wgH, p_wgL, 512);
    wsplit<<<((size_t)9*256*512 + 255)/256, 256>>>(cw, p_wcH, p_wcL, 256);
    wtheta_split<<<(CC*CC + 255)/256, 256>>>(theta_w);

    const int EW = NBCP/256;  // 19200
    const dim3 tgrid(50, 8, 12), tblk(32, 8);
    for (int pass = 0; pass < 2; pass++) {
        tsplit<<<tgrid, tblk>>>(p_nodes, p_nTH, p_nTL);
        theta_mma<<<dim3(2, 13, NBB), 256>>>(theta_b);
        sum_split<<<EW, 256>>>();
        scores_mma<<<dim3(13, 13, EE*BB), 256>>>();
        softmax_fp<<<EE*BB*PP, 256>>>();
        msg_mma<<<dim3(13, 2, EE*BB), 256>>>();
        aggT_t<<<tgrid, tblk>>>();
        conv_mma<<<dim3(13, 4, NBB), 256>>>(p_wgH, p_wgL, gb, p_nTH, p_gates, 512);
        rhT_t<<<tgrid, tblk>>>();
        conv_mma<<<dim3(13, 2, NBB), 256>>>(p_wcH, p_wcL, cb, p_rhH, p_cand, 256);
        update_kernel<<<EW, 256>>>();
    }
    copy_out<<<(NBCP/4 + 255)/256, 256>>>(out);
}

// round 14
// speedup vs baseline: 1.4528x; 1.3061x over previous
#include <cuda_runtime.h>
#include <cuda_fp16.h>
#include <math.h>
#include <stdint.h>

// ---------------- problem constants ----------------
#define NN   3
#define BB   4
#define CC   256
#define HH   40
#define WW   40
#define PP   (HH*WW)           // 1600
#define EE   6
#define NBB  (NN*BB)           // 12
#define CP   (CC*PP)           // 409600
#define BCP  (BB*CP)
#define NBCP (NN*BCP)          // 4915200

// ---------------- scratch ----------------
__device__ float g_nodes [NBCP];
__device__ float g_scores[(size_t)EE*BB*PP*PP];
__device__ float g_msg   [(size_t)EE*BCP];
__device__ float g_gates [(size_t)NBB*512*PP];
__device__ float g_cand  [NBCP];

// fp16 hi/lo split buffers (16B-aligned for cp.async)
__device__ __align__(16) __half g_atnH[(size_t)EE*BB*PP*PP];      // atn hi only
__device__ __align__(16) __half g_nodesTH[NBCP], g_nodesTL[NBCP]; // [z][p][c]
__device__ __align__(16) __half g_thTH[NBCP],    g_thTL[NBCP];    // [z][p][c]
__device__ __align__(16) __half g_sumH[NN*BCP],  g_sumL[NN*BCP];  // [pair*b][c][q]
__device__ __align__(16) __half g_aggTH[NBCP];                    // [z][p][c] (H only)
__device__ __align__(16) __half g_rhTH[NBCP];                     // [z][p][c] (H only)
__device__ __align__(16) __half g_wgH[9*512*512];                 // [s][oc][ci] (H only)
__device__ __align__(16) __half g_wcH[9*256*512];
__device__ __align__(16) __half g_wtH[CC*CC],     g_wtL[CC*CC];   // theta W [o][c]

__device__ __constant__ int c_recv[EE] = {0,0,1,1,2,2};
__device__ __constant__ int c_send[EE] = {1,2,0,2,0,1};
__device__ __constant__ int c_pair[EE] = {0,1,0,2,1,2};
__device__ __constant__ int c_p0[NN]   = {0,0,1};
__device__ __constant__ int c_p1[NN]   = {1,2,2};

// ================= low-level helpers (portable PTX only) =================
__device__ __forceinline__ uint32_t smem_u32(const void* p) {
    uint32_t a;
    asm("{ .reg .u64 t; cvta.to.shared.u64 t, %1; cvt.u32.u64 %0, t; }" : "=r"(a) : "l"(p));
    return a;
}
__device__ __forceinline__ void cp16(uint32_t dst, const void* src, bool v) {
    asm volatile("cp.async.cg.shared.global [%0], [%1], 16, %2;"
                 :: "r"(dst), "l"(src), "r"(v ? 16 : 0));
}
#define CP_COMMIT() asm volatile("cp.async.commit_group;" ::: "memory")
#define CP_WAIT1()  asm volatile("cp.async.wait_group 1;" ::: "memory")

__device__ __forceinline__ void ldsm4(uint32_t (&r)[4], uint32_t addr) {
    asm volatile("ldmatrix.sync.aligned.m8n8.x4.shared.b16 {%0,%1,%2,%3}, [%4];"
                 : "=r"(r[0]), "=r"(r[1]), "=r"(r[2]), "=r"(r[3]) : "r"(addr));
}
__device__ __forceinline__ void mma16816(float* c, const uint32_t (&a)[4],
                                         uint32_t b0, uint32_t b1) {
    asm volatile("mma.sync.aligned.m16n8k16.row.col.f32.f16.f16.f32 "
                 "{%0,%1,%2,%3}, {%4,%5,%6,%7}, {%8,%9}, {%0,%1,%2,%3};"
                 : "+f"(c[0]), "+f"(c[1]), "+f"(c[2]), "+f"(c[3])
                 : "r"(a[0]), "r"(a[1]), "r"(a[2]), "r"(a[3]), "r"(b0), "r"(b1));
}

// ---------------- tile geometry ----------------
#define TSTRIDE 72
#define TILE_B  (128*TSTRIDE*2)   // 18432 bytes per tile buffer

__device__ __forceinline__ void compute_chunk(uint32_t aT, uint32_t bT,
                                              int lane, int wm, int wn,
                                              float (*acc)[4][4]) {
    const int arow = wm*64 + ((lane>>3)&1)*8 + (lane&7);
    const int acol = (lane>>4)*8;
    const int brow = wn*32 + ((lane>>4)&1)*8 + (lane&7);
    const int bcol = ((lane>>3)&1)*8;
#pragma unroll
    for (int ks = 0; ks < 4; ks++) {
        uint32_t a[4][4], b[2][4];
#pragma unroll
        for (int mt = 0; mt < 4; mt++)
            ldsm4(a[mt], aT + (uint32_t)(((arow + mt*16)*TSTRIDE) + acol + ks*16)*2);
#pragma unroll
        for (int np = 0; np < 2; np++)
            ldsm4(b[np], bT + (uint32_t)(((brow + np*16)*TSTRIDE) + bcol + ks*16)*2);
#pragma unroll
        for (int mt = 0; mt < 4; mt++)
#pragma unroll
            for (int nt = 0; nt < 4; nt++)
                mma16816(acc[mt][nt], a[mt], b[nt>>1][(nt&1)*2], b[nt>>1][(nt&1)*2+1]);
    }
}

__device__ __forceinline__ void epilogue(float (*acc)[4][4], float* out,
                                         int m0, int n0, int Mtot, int Ntot,
                                         const float* bias, int lane, int wm, int wn) {
#pragma unroll
    for (int mt = 0; mt < 4; mt++) {
        int m = m0 + wm*64 + mt*16 + (lane>>2);
        float bv0 = (bias && m < Mtot) ? bias[m] : 0.f;
        float bv1 = (bias && m+8 < Mtot) ? bias[m+8] : 0.f;
#pragma unroll
        for (int nt = 0; nt < 4; nt++) {
            int n = n0 + wn*32 + nt*8 + (lane&3)*2;
            if (n >= Ntot) continue;
            if (m < Mtot) {
                float2 v = make_float2(acc[mt][nt][0] + bv0, acc[mt][nt][1] + bv0);
                *(float2*)&out[(size_t)m*Ntot + n] = v;
            }
            if (m+8 < Mtot) {
                float2 v = make_float2(acc[mt][nt][2] + bv1, acc[mt][nt][3] + bv1);
                *(float2*)&out[(size_t)(m+8)*Ntot + n] = v;
            }
        }
    }
}

// Pair-iteration mainloop: 2 buffers, 1-deep lookahead.
#define MAINLOOP(NIT, ISPAIR)                                                     \
    stage(0, 0); CP_COMMIT();                                                     \
    for (int t = 0; t < (NIT); t++) {                                             \
        if (t+1 < (NIT)) stage(t+1, (t+1)&1);                                     \
        CP_COMMIT();                                                              \
        CP_WAIT1(); __syncthreads();                                              \
        uint32_t bufo = (uint32_t)(t&1)*TILE_B;                                   \
        compute_chunk(sAh + bufo, sB + bufo, lane, wm, wn, acc);                  \
        if (ISPAIR) compute_chunk(sAl + bufo, sB + bufo, lane, wm, wn, acc);      \
        __syncthreads();                                                          \
    }

// ============ scores: S[p][q] = sum_c th[p][c]*nodes[q][c], 3-seg paired ============
__global__ __launch_bounds__(256) void scores_mma() {
    __shared__ alignas(16) __half Ah[2][128][TSTRIDE];
    __shared__ alignas(16) __half Al[2][128][TSTRIDE];
    __shared__ alignas(16) __half Bs[2][128][TSTRIDE];
    const int tid = threadIdx.x, lane = tid & 31, wid = tid >> 5;
    const int wm = wid & 1, wn = wid >> 1;
    const int z = blockIdx.z, e = z >> 2, b = z & 3;
    const int zr = c_recv[e]*BB + b, zs = c_send[e]*BB + b;
    const int m0 = blockIdx.y*128, n0 = blockIdx.x*128;
    float* Cp = g_scores + (size_t)z*PP*PP;
    const uint32_t sAh = smem_u32(Ah), sAl = smem_u32(Al), sB = smem_u32(Bs);

    const int r0 = tid >> 2, seg8 = (tid & 3)*8;
    float acc[4][4][4] = {};

    auto stage = [&](int it, int buf) {
        bool pair = it < 4;
        int k0 = (pair ? it : it - 4)*64;
        const __half* bS = pair ? g_nodesTH : g_nodesTL;
        uint32_t aTh = sAh + buf*TILE_B, aTl = sAl + buf*TILE_B, bT = sB + buf*TILE_B;
#pragma unroll
        for (int i = 0; i < 2; i++) {
            int row = r0 + i*64;
            int gm = m0 + row, gn = n0 + row;
            bool va = gm < PP, vb = gn < PP;
            size_t aoff = ((size_t)zr*PP + (va ? gm : 0))*256 + k0;
            size_t boff = ((size_t)zs*PP + (vb ? gn : 0))*256 + k0;
#pragma unroll
            for (int j = 0; j < 2; j++) {
                int koff = seg8 + j*32;
                uint32_t o = (uint32_t)(row*TSTRIDE + koff)*2;
                cp16(aTh + o, g_thTH + aoff + koff, va);
                if (pair) cp16(aTl + o, g_thTL + aoff + koff, va);
                cp16(bT + o, bS + boff + koff, vb);
            }
        }
    };

    MAINLOOP(8, (t < 4))
    epilogue(acc, Cp, m0, n0, PP, PP, nullptr, lane, wm, wn);
}

// ============ msg: M[c][p] = sum_q sum[c][q]*atn[p][q], 2-seg paired ============
__global__ __launch_bounds__(256) void msg_mma() {
    __shared__ alignas(16) __half Ah[2][128][TSTRIDE];
    __shared__ alignas(16) __half Al[2][128][TSTRIDE];
    __shared__ alignas(16) __half Bs[2][128][TSTRIDE];
    const int tid = threadIdx.x, lane = tid & 31, wid = tid >> 5;
    const int wm = wid & 1, wn = wid >> 1;
    const int z = blockIdx.z, e = z >> 2, b = z & 3;
    const int zp = c_pair[e]*BB + b;
    const int m0 = blockIdx.y*128, n0 = blockIdx.x*128;
    float* Cp = g_msg + (size_t)z*CP;
    const uint32_t sAh = smem_u32(Ah), sAl = smem_u32(Al), sB = smem_u32(Bs);

    const int r0 = tid >> 2, seg8 = (tid & 3)*8;
    float acc[4][4][4] = {};

    auto stage = [&](int it, int buf) {
        int k0 = it*64;
        uint32_t aTh = sAh + buf*TILE_B, aTl = sAl + buf*TILE_B, bT = sB + buf*TILE_B;
#pragma unroll
        for (int i = 0; i < 2; i++) {
            int row = r0 + i*64;
            int gn = n0 + row;
            bool vb = gn < PP;
            size_t aoff = ((size_t)zp*CC + m0 + row)*PP + k0;
            size_t boff = ((size_t)z*PP + (vb ? gn : 0))*PP + k0;
#pragma unroll
            for (int j = 0; j < 2; j++) {
                int koff = seg8 + j*32;
                uint32_t o = (uint32_t)(row*TSTRIDE + koff)*2;
                cp16(aTh + o, g_sumH + aoff + koff, true);
                cp16(aTl + o, g_sumL + aoff + koff, true);
                cp16(bT + o, g_atnH + boff + koff, vb);
            }
        }
    };

    MAINLOOP(25, true)
    epilogue(acc, Cp, m0, n0, CC, PP, nullptr, lane, wm, wn);
}

// ============ conv3x3 as GEMM: 1-SEG (wH x xH only), 72 single iters ============
// Dropped wL correction (~2^-12 rel on gate logits; sigmoid/tanh attenuate further).
__global__ __launch_bounds__(256) void conv_mma(const __half* __restrict__ wH,
                                                const float* __restrict__ bias,
                                                const __half* __restrict__ x1H,
                                                float* __restrict__ out, int OC) {
    __shared__ alignas(16) __half Ah[2][128][TSTRIDE];
    __shared__ alignas(16) __half Bs[2][128][TSTRIDE];
    const int tid = threadIdx.x, lane = tid & 31, wid = tid >> 5;
    const int wm = wid & 1, wn = wid >> 1;
    const int z = blockIdx.z;
    const int m0 = blockIdx.y*128, n0 = blockIdx.x*128;
    float* pO = out + (size_t)z*OC*PP;
    const uint32_t sAh = smem_u32(Ah), sB = smem_u32(Bs);

    const int r0 = tid >> 2, seg8 = (tid & 3)*8;
    int gn0 = n0 + r0,        y0 = gn0 / WW, x0 = gn0 % WW;
    int gn1 = n0 + r0 + 64,   y1 = gn1 / WW, x1c = gn1 % WW;
    float acc[4][4][4] = {};

    auto stage = [&](int it, int buf) {
        int kk = it*64;
        int s  = kk >> 9;
        int cw = kk & 511;               // 0,64,...,448
        int ky = s/3 - 1, kx = s%3 - 1;
        const __half* bS = (cw < 256) ? g_aggTH : x1H;
        int ci = cw & 255;
        uint32_t aTh = sAh + buf*TILE_B, bT = sB + buf*TILE_B;
#pragma unroll
        for (int i = 0; i < 2; i++) {
            int row = r0 + i*64;
            size_t aoff = ((size_t)s*OC + m0 + row)*512 + cw;
            int yy = (i ? y1 : y0) + ky, xx = (i ? x1c : x0) + kx;
            int gnr = i ? gn1 : gn0;
            bool vb = (gnr < PP) && yy >= 0 && yy < HH && xx >= 0 && xx < WW;
            int sp = vb ? (yy*WW + xx) : 0;
            size_t boff = ((size_t)z*PP + sp)*256 + ci;
#pragma unroll
            for (int j = 0; j < 2; j++) {
                int koff = seg8 + j*32;
                uint32_t o = (uint32_t)(row*TSTRIDE + koff)*2;
                cp16(aTh + o, wH + aoff + koff, true);
                cp16(bT + o, bS + boff + koff, vb);
            }
        }
    };

    stage(0, 0); CP_COMMIT();
    for (int t = 0; t < 72; t++) {
        if (t+1 < 72) stage(t+1, (t+1)&1);
        CP_COMMIT();
        CP_WAIT1(); __syncthreads();
        uint32_t bufo = (uint32_t)(t&1)*TILE_B;
        compute_chunk(sAh + bufo, sB + bufo, lane, wm, wn, acc);
        __syncthreads();
    }
    epilogue(acc, pO, m0, n0, OC, PP, bias, lane, wm, wn);
}

// ============ theta: thT[p][o] = sum_c nodesT[p][c]*W[o][c] + b[o], 3-seg paired ============
__global__ __launch_bounds__(256) void theta_mma(const float* __restrict__ bias) {
    __shared__ alignas(16) __half Ah[2][128][TSTRIDE];
    __shared__ alignas(16) __half Al[2][128][TSTRIDE];
    __shared__ alignas(16) __half Bs[2][128][TSTRIDE];
    const int tid = threadIdx.x, lane = tid & 31, wid = tid >> 5;
    const int wm = wid & 1, wn = wid >> 1;
    const int z = blockIdx.z;
    const int m0 = blockIdx.y*128, n0 = blockIdx.x*128;
    const uint32_t sAh = smem_u32(Ah), sAl = smem_u32(Al), sB = smem_u32(Bs);

    const int r0 = tid >> 2, seg8 = (tid & 3)*8;
    float acc[4][4][4] = {};

    auto stage = [&](int it, int buf) {
        bool pair = it < 4;
        int k0 = (it & 3)*64;
        const __half* bS = pair ? g_wtH : g_wtL;
        uint32_t aTh = sAh + buf*TILE_B, aTl = sAl + buf*TILE_B, bT = sB + buf*TILE_B;
#pragma unroll
        for (int i = 0; i < 2; i++) {
            int row = r0 + i*64;
            int gm = m0 + row;
            bool va = gm < PP;
            size_t aoff = ((size_t)z*PP + (va ? gm : 0))*256 + k0;
            size_t boff = (size_t)(n0 + row)*256 + k0;
#pragma unroll
            for (int j = 0; j < 2; j++) {
                int koff = seg8 + j*32;
                uint32_t o = (uint32_t)(row*TSTRIDE + koff)*2;
                cp16(aTh + o, g_nodesTH + aoff + koff, va);
                if (pair) cp16(aTl + o, g_nodesTL + aoff + koff, va);
                cp16(bT + o, bS + boff + koff, true);
            }
        }
    };

    MAINLOOP(8, (t < 4))

#pragma unroll
    for (int mt = 0; mt < 4; mt++) {
        int m = m0 + wm*64 + mt*16 + (lane>>2);
#pragma unroll
        for (int nt = 0; nt < 4; nt++) {
            int n = n0 + wn*32 + nt*8 + (lane&3)*2;
            float bv0 = bias[n], bv1 = bias[n+1];
#pragma unroll
            for (int half = 0; half < 2; half++) {
                int mm = m + half*8;
                if (mm >= PP) continue;
                float v0 = acc[mt][nt][half*2+0] + bv0;
                float v1 = acc[mt][nt][half*2+1] + bv1;
                __half h0 = __float2half_rn(v0);
                __half h1 = __float2half_rn(v1);
                __half l0 = __float2half_rn(v0 - __half2float(h0));
                __half l1 = __float2half_rn(v1 - __half2float(h1));
                size_t o = ((size_t)z*PP + mm)*256 + n;
                *(__half2*)&g_thTH[o] = __halves2half2(h0, h1);
                *(__half2*)&g_thTL[o] = __halves2half2(l0, l1);
            }
        }
    }
}

// ============ softmax rows -> fp16 attention (hi only) ============
__device__ __forceinline__ float block_reduce(float v, bool is_max) {
    __shared__ float s[32];
    __syncthreads();
#pragma unroll
    for (int o = 16; o > 0; o >>= 1) {
        float t = __shfl_xor_sync(0xffffffffu, v, o);
        v = is_max ? fmaxf(v, t) : (v + t);
    }
    const int w = threadIdx.x >> 5, l = threadIdx.x & 31;
    if (l == 0) s[w] = v;
    __syncthreads();
    if (w == 0) {
        v = (l < 8) ? s[l] : (is_max ? -INFINITY : 0.f);
#pragma unroll
        for (int o = 4; o > 0; o >>= 1) {
            float t = __shfl_xor_sync(0xffffffffu, v, o);
            v = is_max ? fmaxf(v, t) : (v + t);
        }
        if (l == 0) s[0] = v;
    }
    __syncthreads();
    return s[0];
}

__global__ __launch_bounds__(256) void softmax_fp() {
    const size_t row = blockIdx.x;
    const float* srow = g_scores + row*PP;
    __half* hrow = g_atnH + row*PP;
    const int t = threadIdx.x;
    float v[7];
    float mx = -INFINITY;
#pragma unroll
    for (int i = 0; i < 7; i++) {
        int idx = t + i*256;
        v[i] = (idx < PP) ? srow[idx] : -INFINITY;
        mx = fmaxf(mx, v[i]);
    }
    mx = block_reduce(mx, true);
    float sum = 0.f;
#pragma unroll
    for (int i = 0; i < 7; i++) {
        int idx = t + i*256;
        if (idx < PP) { v[i] = __expf(v[i] - mx); sum += v[i]; }
    }
    sum = block_reduce(sum, false);
    const float inv = 1.f / sum;
#pragma unroll
    for (int i = 0; i < 7; i++) {
        int idx = t + i*256;
        if (idx < PP) hrow[idx] = __float2half_rn(v[i] * inv);
    }
}

// ============ split / transpose prep kernels ============
__device__ __forceinline__ void hsplit(float v, __half* h, __half* l) {
    __half hh = __float2half_rn(v);
    *h = hh;
    *l = __float2half_rn(v - __half2float(hh));
}

__global__ __launch_bounds__(256) void tsplit(const float* __restrict__ src,
                                              __half* __restrict__ dh,
                                              __half* __restrict__ dl) {
    __shared__ float tile[32][33];
    const int z = blockIdx.z, p0 = blockIdx.x*32, c0 = blockIdx.y*32;
    const int tx = threadIdx.x, ty = threadIdx.y;
    const float* s = src + (size_t)z*CP;
#pragma unroll
    for (int k = 0; k < 4; k++)
        tile[ty + 8*k][tx] = s[(size_t)(c0 + ty + 8*k)*PP + p0 + tx];
    __syncthreads();
#pragma unroll
    for (int k = 0; k < 4; k++) {
        float v = tile[tx][ty + 8*k];
        size_t o = ((size_t)z*PP + p0 + ty + 8*k)*256 + c0 + tx;
        hsplit(v, &dh[o], &dl[o]);
    }
}

__global__ __launch_bounds__(256) void aggT_t() {
    __shared__ float tile[32][33];
    const int z = blockIdx.z, p0 = blockIdx.x*32, c0 = blockIdx.y*32;
    const int n = z >> 2, b = z & 3;
    const int tx = threadIdx.x, ty = threadIdx.y;
    const float* m1 = g_msg + (size_t)(8*n + b)*CP;
    const float* m2 = g_msg + (size_t)(8*n + 4 + b)*CP;
#pragma unroll
    for (int k = 0; k < 4; k++) {
        size_t o = (size_t)(c0 + ty + 8*k)*PP + p0 + tx;
        tile[ty + 8*k][tx] = m1[o] + m2[o];
    }
    __syncthreads();
#pragma unroll
    for (int k = 0; k < 4; k++) {
        size_t o = ((size_t)z*PP + p0 + ty + 8*k)*256 + c0 + tx;
        g_aggTH[o] = __float2half_rn(tile[tx][ty + 8*k]);
    }
}

__global__ __launch_bounds__(256) void rhT_t() {
    __shared__ float tile[32][33];
    const int z = blockIdx.z, p0 = blockIdx.x*32, c0 = blockIdx.y*32;
    const int tx = threadIdx.x, ty = threadIdx.y;
    const float* gp = g_gates + (size_t)z*512*PP;
    const float* hp = g_nodes + (size_t)z*CP;
#pragma unroll
    for (int k = 0; k < 4; k++) {
        size_t o = (size_t)(c0 + ty + 8*k)*PP + p0 + tx;
        float g = gp[o];
        float r = 1.f / (1.f + __expf(-g));
        tile[ty + 8*k][tx] = r * hp[o];
    }
    __syncthreads();
#pragma unroll
    for (int k = 0; k < 4; k++) {
        size_t o = ((size_t)z*PP + p0 + ty + 8*k)*256 + c0 + tx;
        g_rhTH[o] = __float2half_rn(tile[tx][ty + 8*k]);
    }
}

__global__ __launch_bounds__(256) void sum_split() {
    size_t i = (size_t)blockIdx.x*256 + threadIdx.x;
    if (i >= (size_t)NN*BCP) return;
    int z2 = (int)(i / CP); size_t cp = i % CP;
    int pr = z2 >> 2, b = z2 & 3;
    float v = g_nodes[(size_t)(c_p0[pr]*BB + b)*CP + cp] +
              g_nodes[(size_t)(c_p1[pr]*BB + b)*CP + cp];
    hsplit(v, &g_sumH[i], &g_sumL[i]);
}

__global__ __launch_bounds__(256) void update_kernel() {
    size_t i = (size_t)blockIdx.x*256 + threadIdx.x;
    if (i >= (size_t)NBCP) return;
    size_t nb = i / CP, cp = i % CP;
    float gz = g_gates[nb*(size_t)(512*PP) + (size_t)CC*PP + cp];
    float zv = 1.f / (1.f + __expf(-gz));
    float h = g_nodes[i];
    float cd = tanhf(g_cand[i]);
    g_nodes[i] = (1.f - zv)*h + zv*cd;
}

// conv weights: w[oc][ci][3][3] -> [s][oc][ci] fp16 (H only)
__global__ __launch_bounds__(256) void wsplit_h(const float* __restrict__ w,
                                                __half* __restrict__ dh, int OC) {
    size_t i = (size_t)blockIdx.x*256 + threadIdx.x;
    size_t total = (size_t)9*OC*512;
    if (i >= total) return;
    int ci = (int)(i & 511);
    int oc = (int)((i >> 9) % OC);
    int s  = (int)(i / ((size_t)OC*512));
    dh[i] = __float2half_rn(w[((size_t)oc*512 + ci)*9 + s]);
}

__global__ __launch_bounds__(256) void wtheta_split(const float* __restrict__ w) {
    int i = blockIdx.x*256 + threadIdx.x;
    if (i >= CC*CC) return;
    hsplit(w[i], &g_wtH[i], &g_wtL[i]);
}

__global__ __launch_bounds__(256) void copy_in(const float* __restrict__ src) {
    size_t i = (size_t)blockIdx.x*256 + threadIdx.x;
    if (i < (size_t)NBCP/4) ((float4*)g_nodes)[i] = ((const float4*)src)[i];
}
__global__ __launch_bounds__(256) void copy_out(float* __restrict__ dst) {
    size_t i = (size_t)blockIdx.x*256 + threadIdx.x;
    if (i < (size_t)NBCP/4) ((float4*)dst)[i] = ((const float4*)g_nodes)[i];
}

// ---------------- host launch ----------------
extern "C" void kernel_launch(void* const* d_in, const int* in_sizes, int n_in,
                              void* d_out, int out_size) {
    const float* in_nodes = (const float*)d_in[0];
    const float* theta_w  = (const float*)d_in[1];
    const float* theta_b  = (const float*)d_in[2];
    const float* gw       = (const float*)d_in[3];
    const float* gb       = (const float*)d_in[4];
    const float* cw       = (const float*)d_in[5];
    const float* cb       = (const float*)d_in[6];
    float* out = (float*)d_out;

    __half *p_wgH, *p_wcH, *p_nTH, *p_nTL, *p_rhH;
    float *p_nodes, *p_gates, *p_cand;
    cudaGetSymbolAddress((void**)&p_wgH, g_wgH);
    cudaGetSymbolAddress((void**)&p_wcH, g_wcH);
    cudaGetSymbolAddress((void**)&p_nTH, g_nodesTH);
    cudaGetSymbolAddress((void**)&p_nTL, g_nodesTL);
    cudaGetSymbolAddress((void**)&p_rhH, g_rhTH);
    cudaGetSymbolAddress((void**)&p_nodes, g_nodes);
    cudaGetSymbolAddress((void**)&p_gates, g_gates);
    cudaGetSymbolAddress((void**)&p_cand,  g_cand);

    copy_in<<<(NBCP/4 + 255)/256, 256>>>(in_nodes);
    wsplit_h<<<((size_t)9*512*512 + 255)/256, 256>>>(gw, p_wgH, 512);
    wsplit_h<<<((size_t)9*256*512 + 255)/256, 256>>>(cw, p_wcH, 256);
    wtheta_split<<<(CC*CC + 255)/256, 256>>>(theta_w);

    const int EW = NBCP/256;  // 19200
    const dim3 tgrid(50, 8, 12), tblk(32, 8);
    for (int pass = 0; pass < 2; pass++) {
        tsplit<<<tgrid, tblk>>>(p_nodes, p_nTH, p_nTL);
        theta_mma<<<dim3(2, 13, NBB), 256>>>(theta_b);
        sum_split<<<EW, 256>>>();
        scores_mma<<<dim3(13, 13, EE*BB), 256>>>();
        softmax_fp<<<EE*BB*PP, 256>>>();
        msg_mma<<<dim3(13, 2, EE*BB), 256>>>();
        aggT_t<<<tgrid, tblk>>>();
        conv_mma<<<dim3(13, 4, NBB), 256>>>(p_wgH, gb, p_nTH, p_gates, 512);
        rhT_t<<<tgrid, tblk>>>();
        conv_mma<<<dim3(13, 2, NBB), 256>>>(p_wcH, cb, p_rhH, p_cand, 256);
        update_kernel<<<EW, 256>>>();
    }
    copy_out<<<(NBCP/4 + 255)/256, 256>>>(out);
}

// round 15
// speedup vs baseline: 1.5651x; 1.0773x over previous
#include <cuda_runtime.h>
#include <cuda_fp16.h>
#include <math.h>
#include <stdint.h>

// ---------------- problem constants ----------------
#define NN   3
#define BB   4
#define CC   256
#define HH   40
#define WW   40
#define PP   (HH*WW)           // 1600
#define EE   6
#define NBB  (NN*BB)           // 12
#define CP   (CC*PP)           // 409600
#define BCP  (BB*CP)
#define NBCP (NN*BCP)          // 4915200

// ---------------- scratch ----------------
__device__ float g_nodes [NBCP];
__device__ float g_scores[(size_t)EE*BB*PP*PP];
__device__ float g_msg   [(size_t)EE*BCP];
__device__ float g_gates [(size_t)NBB*512*PP];
__device__ float g_cand  [NBCP];

// fp16 hi/lo split buffers (16B-aligned for cp.async)
__device__ __align__(16) __half g_atnH[(size_t)EE*BB*PP*PP];      // atn hi only
__device__ __align__(16) __half g_nodesTH[NBCP], g_nodesTL[NBCP]; // [z][p][c]
__device__ __align__(16) __half g_thTH[NBCP],    g_thTL[NBCP];    // [z][p][c]
__device__ __align__(16) __half g_sumH[NN*BCP];                   // [pair*b][c][q] (H only)
__device__ __align__(16) __half g_aggTH[NBCP];                    // [z][p][c] (H only)
__device__ __align__(16) __half g_rhTH[NBCP];                     // [z][p][c] (H only)
__device__ __align__(16) __half g_wgH[9*512*512];                 // [s][oc][ci] (H only)
__device__ __align__(16) __half g_wcH[9*256*512];
__device__ __align__(16) __half g_wtH[CC*CC],     g_wtL[CC*CC];   // theta W [o][c]

__device__ __constant__ int c_recv[EE] = {0,0,1,1,2,2};
__device__ __constant__ int c_send[EE] = {1,2,0,2,0,1};
__device__ __constant__ int c_pair[EE] = {0,1,0,2,1,2};
__device__ __constant__ int c_p0[NN]   = {0,0,1};
__device__ __constant__ int c_p1[NN]   = {1,2,2};

// ================= low-level helpers (portable PTX only) =================
__device__ __forceinline__ uint32_t smem_u32(const void* p) {
    uint32_t a;
    asm("{ .reg .u64 t; cvta.to.shared.u64 t, %1; cvt.u32.u64 %0, t; }" : "=r"(a) : "l"(p));
    return a;
}
__device__ __forceinline__ void cp16(uint32_t dst, const void* src, bool v) {
    asm volatile("cp.async.cg.shared.global [%0], [%1], 16, %2;"
                 :: "r"(dst), "l"(src), "r"(v ? 16 : 0));
}
#define CP_COMMIT() asm volatile("cp.async.commit_group;" ::: "memory")
#define CP_WAIT1()  asm volatile("cp.async.wait_group 1;" ::: "memory")

__device__ __forceinline__ void ldsm4(uint32_t (&r)[4], uint32_t addr) {
    asm volatile("ldmatrix.sync.aligned.m8n8.x4.shared.b16 {%0,%1,%2,%3}, [%4];"
                 : "=r"(r[0]), "=r"(r[1]), "=r"(r[2]), "=r"(r[3]) : "r"(addr));
}
__device__ __forceinline__ void mma16816(float* c, const uint32_t (&a)[4],
                                         uint32_t b0, uint32_t b1) {
    asm volatile("mma.sync.aligned.m16n8k16.row.col.f32.f16.f16.f32 "
                 "{%0,%1,%2,%3}, {%4,%5,%6,%7}, {%8,%9}, {%0,%1,%2,%3};"
                 : "+f"(c[0]), "+f"(c[1]), "+f"(c[2]), "+f"(c[3])
                 : "r"(a[0]), "r"(a[1]), "r"(a[2]), "r"(a[3]), "r"(b0), "r"(b1));
}

// ---------------- tile geometry ----------------
#define TSTRIDE 72
#define TILE_B  (128*TSTRIDE*2)   // 18432 bytes per tile buffer

__device__ __forceinline__ void compute_chunk(uint32_t aT, uint32_t bT,
                                              int lane, int wm, int wn,
                                              float (*acc)[4][4]) {
    const int arow = wm*64 + ((lane>>3)&1)*8 + (lane&7);
    const int acol = (lane>>4)*8;
    const int brow = wn*32 + ((lane>>4)&1)*8 + (lane&7);
    const int bcol = ((lane>>3)&1)*8;
#pragma unroll
    for (int ks = 0; ks < 4; ks++) {
        uint32_t a[4][4], b[2][4];
#pragma unroll
        for (int mt = 0; mt < 4; mt++)
            ldsm4(a[mt], aT + (uint32_t)(((arow + mt*16)*TSTRIDE) + acol + ks*16)*2);
#pragma unroll
        for (int np = 0; np < 2; np++)
            ldsm4(b[np], bT + (uint32_t)(((brow + np*16)*TSTRIDE) + bcol + ks*16)*2);
#pragma unroll
        for (int mt = 0; mt < 4; mt++)
#pragma unroll
            for (int nt = 0; nt < 4; nt++)
                mma16816(acc[mt][nt], a[mt], b[nt>>1][(nt&1)*2], b[nt>>1][(nt&1)*2+1]);
    }
}

__device__ __forceinline__ void epilogue(float (*acc)[4][4], float* out,
                                         int m0, int n0, int Mtot, int Ntot,
                                         const float* bias, int lane, int wm, int wn) {
#pragma unroll
    for (int mt = 0; mt < 4; mt++) {
        int m = m0 + wm*64 + mt*16 + (lane>>2);
        float bv0 = (bias && m < Mtot) ? bias[m] : 0.f;
        float bv1 = (bias && m+8 < Mtot) ? bias[m+8] : 0.f;
#pragma unroll
        for (int nt = 0; nt < 4; nt++) {
            int n = n0 + wn*32 + nt*8 + (lane&3)*2;
            if (n >= Ntot) continue;
            if (m < Mtot) {
                float2 v = make_float2(acc[mt][nt][0] + bv0, acc[mt][nt][1] + bv0);
                *(float2*)&out[(size_t)m*Ntot + n] = v;
            }
            if (m+8 < Mtot) {
                float2 v = make_float2(acc[mt][nt][2] + bv1, acc[mt][nt][3] + bv1);
                *(float2*)&out[(size_t)(m+8)*Ntot + n] = v;
            }
        }
    }
}

// Pair-iteration mainloop: 2 buffers, 1-deep lookahead.
#define MAINLOOP(NIT, ISPAIR)                                                     \
    stage(0, 0); CP_COMMIT();                                                     \
    for (int t = 0; t < (NIT); t++) {                                             \
        if (t+1 < (NIT)) stage(t+1, (t+1)&1);                                     \
        CP_COMMIT();                                                              \
        CP_WAIT1(); __syncthreads();                                              \
        uint32_t bufo = (uint32_t)(t&1)*TILE_B;                                   \
        compute_chunk(sAh + bufo, sB + bufo, lane, wm, wn, acc);                  \
        if (ISPAIR) compute_chunk(sAl + bufo, sB + bufo, lane, wm, wn, acc);      \
        __syncthreads();                                                          \
    }

// ============ scores: S[p][q] = sum_c th[p][c]*nodes[q][c], 3-seg paired ============
__global__ __launch_bounds__(256) void scores_mma() {
    __shared__ alignas(16) __half Ah[2][128][TSTRIDE];
    __shared__ alignas(16) __half Al[2][128][TSTRIDE];
    __shared__ alignas(16) __half Bs[2][128][TSTRIDE];
    const int tid = threadIdx.x, lane = tid & 31, wid = tid >> 5;
    const int wm = wid & 1, wn = wid >> 1;
    const int z = blockIdx.z, e = z >> 2, b = z & 3;
    const int zr = c_recv[e]*BB + b, zs = c_send[e]*BB + b;
    const int m0 = blockIdx.y*128, n0 = blockIdx.x*128;
    float* Cp = g_scores + (size_t)z*PP*PP;
    const uint32_t sAh = smem_u32(Ah), sAl = smem_u32(Al), sB = smem_u32(Bs);

    const int r0 = tid >> 2, seg8 = (tid & 3)*8;
    float acc[4][4][4] = {};

    auto stage = [&](int it, int buf) {
        bool pair = it < 4;
        int k0 = (pair ? it : it - 4)*64;
        const __half* bS = pair ? g_nodesTH : g_nodesTL;
        uint32_t aTh = sAh + buf*TILE_B, aTl = sAl + buf*TILE_B, bT = sB + buf*TILE_B;
#pragma unroll
        for (int i = 0; i < 2; i++) {
            int row = r0 + i*64;
            int gm = m0 + row, gn = n0 + row;
            bool va = gm < PP, vb = gn < PP;
            size_t aoff = ((size_t)zr*PP + (va ? gm : 0))*256 + k0;
            size_t boff = ((size_t)zs*PP + (vb ? gn : 0))*256 + k0;
#pragma unroll
            for (int j = 0; j < 2; j++) {
                int koff = seg8 + j*32;
                uint32_t o = (uint32_t)(row*TSTRIDE + koff)*2;
                cp16(aTh + o, g_thTH + aoff + koff, va);
                if (pair) cp16(aTl + o, g_thTL + aoff + koff, va);
                cp16(bT + o, bS + boff + koff, vb);
            }
        }
    };

    MAINLOOP(8, (t < 4))
    epilogue(acc, Cp, m0, n0, PP, PP, nullptr, lane, wm, wn);
}

// ============ msg: M[c][p] = sum_q sumH[c][q]*atnH[p][q], 1-SEG, 25 iters ============
// (sumL and atnL corrections both dropped: each ~2^-12 rel on msg)
__global__ __launch_bounds__(256) void msg_mma() {
    __shared__ alignas(16) __half Ah[2][128][TSTRIDE];
    __shared__ alignas(16) __half Bs[2][128][TSTRIDE];
    const int tid = threadIdx.x, lane = tid & 31, wid = tid >> 5;
    const int wm = wid & 1, wn = wid >> 1;
    const int z = blockIdx.z, e = z >> 2, b = z & 3;
    const int zp = c_pair[e]*BB + b;
    const int m0 = blockIdx.y*128, n0 = blockIdx.x*128;
    float* Cp = g_msg + (size_t)z*CP;
    const uint32_t sAh = smem_u32(Ah), sB = smem_u32(Bs);

    const int r0 = tid >> 2, seg8 = (tid & 3)*8;
    float acc[4][4][4] = {};

    auto stage = [&](int it, int buf) {
        int k0 = it*64;
        uint32_t aTh = sAh + buf*TILE_B, bT = sB + buf*TILE_B;
#pragma unroll
        for (int i = 0; i < 2; i++) {
            int row = r0 + i*64;
            int gn = n0 + row;
            bool vb = gn < PP;
            size_t aoff = ((size_t)zp*CC + m0 + row)*PP + k0;
            size_t boff = ((size_t)z*PP + (vb ? gn : 0))*PP + k0;
#pragma unroll
            for (int j = 0; j < 2; j++) {
                int koff = seg8 + j*32;
                uint32_t o = (uint32_t)(row*TSTRIDE + koff)*2;
                cp16(aTh + o, g_sumH + aoff + koff, true);
                cp16(bT + o, g_atnH + boff + koff, vb);
            }
        }
    };

    stage(0, 0); CP_COMMIT();
    for (int t = 0; t < 25; t++) {
        if (t+1 < 25) stage(t+1, (t+1)&1);
        CP_COMMIT();
        CP_WAIT1(); __syncthreads();
        uint32_t bufo = (uint32_t)(t&1)*TILE_B;
        compute_chunk(sAh + bufo, sB + bufo, lane, wm, wn, acc);
        __syncthreads();
    }
    epilogue(acc, Cp, m0, n0, CC, PP, nullptr, lane, wm, wn);
}

// ============ conv3x3 as GEMM: 1-SEG (wH x xH only), 72 single iters ============
__global__ __launch_bounds__(256) void conv_mma(const __half* __restrict__ wH,
                                                const float* __restrict__ bias,
                                                const __half* __restrict__ x1H,
                                                float* __restrict__ out, int OC) {
    __shared__ alignas(16) __half Ah[2][128][TSTRIDE];
    __shared__ alignas(16) __half Bs[2][128][TSTRIDE];
    const int tid = threadIdx.x, lane = tid & 31, wid = tid >> 5;
    const int wm = wid & 1, wn = wid >> 1;
    const int z = blockIdx.z;
    const int m0 = blockIdx.y*128, n0 = blockIdx.x*128;
    float* pO = out + (size_t)z*OC*PP;
    const uint32_t sAh = smem_u32(Ah), sB = smem_u32(Bs);

    const int r0 = tid >> 2, seg8 = (tid & 3)*8;
    int gn0 = n0 + r0,        y0 = gn0 / WW, x0 = gn0 % WW;
    int gn1 = n0 + r0 + 64,   y1 = gn1 / WW, x1c = gn1 % WW;
    float acc[4][4][4] = {};

    auto stage = [&](int it, int buf) {
        int kk = it*64;
        int s  = kk >> 9;
        int cw = kk & 511;               // 0,64,...,448
        int ky = s/3 - 1, kx = s%3 - 1;
        const __half* bS = (cw < 256) ? g_aggTH : x1H;
        int ci = cw & 255;
        uint32_t aTh = sAh + buf*TILE_B, bT = sB + buf*TILE_B;
#pragma unroll
        for (int i = 0; i < 2; i++) {
            int row = r0 + i*64;
            size_t aoff = ((size_t)s*OC + m0 + row)*512 + cw;
            int yy = (i ? y1 : y0) + ky, xx = (i ? x1c : x0) + kx;
            int gnr = i ? gn1 : gn0;
            bool vb = (gnr < PP) && yy >= 0 && yy < HH && xx >= 0 && xx < WW;
            int sp = vb ? (yy*WW + xx) : 0;
            size_t boff = ((size_t)z*PP + sp)*256 + ci;
#pragma unroll
            for (int j = 0; j < 2; j++) {
                int koff = seg8 + j*32;
                uint32_t o = (uint32_t)(row*TSTRIDE + koff)*2;
                cp16(aTh + o, wH + aoff + koff, true);
                cp16(bT + o, bS + boff + koff, vb);
            }
        }
    };

    stage(0, 0); CP_COMMIT();
    for (int t = 0; t < 72; t++) {
        if (t+1 < 72) stage(t+1, (t+1)&1);
        CP_COMMIT();
        CP_WAIT1(); __syncthreads();
        uint32_t bufo = (uint32_t)(t&1)*TILE_B;
        compute_chunk(sAh + bufo, sB + bufo, lane, wm, wn, acc);
        __syncthreads();
    }
    epilogue(acc, pO, m0, n0, OC, PP, bias, lane, wm, wn);
}

// ============ theta: thT[p][o] = sum_c nodesT[p][c]*W[o][c] + b[o], 3-seg paired ============
__global__ __launch_bounds__(256) void theta_mma(const float* __restrict__ bias) {
    __shared__ alignas(16) __half Ah[2][128][TSTRIDE];
    __shared__ alignas(16) __half Al[2][128][TSTRIDE];
    __shared__ alignas(16) __half Bs[2][128][TSTRIDE];
    const int tid = threadIdx.x, lane = tid & 31, wid = tid >> 5;
    const int wm = wid & 1, wn = wid >> 1;
    const int z = blockIdx.z;
    const int m0 = blockIdx.y*128, n0 = blockIdx.x*128;
    const uint32_t sAh = smem_u32(Ah), sAl = smem_u32(Al), sB = smem_u32(Bs);

    const int r0 = tid >> 2, seg8 = (tid & 3)*8;
    float acc[4][4][4] = {};

    auto stage = [&](int it, int buf) {
        bool pair = it < 4;
        int k0 = (it & 3)*64;
        const __half* bS = pair ? g_wtH : g_wtL;
        uint32_t aTh = sAh + buf*TILE_B, aTl = sAl + buf*TILE_B, bT = sB + buf*TILE_B;
#pragma unroll
        for (int i = 0; i < 2; i++) {
            int row = r0 + i*64;
            int gm = m0 + row;
            bool va = gm < PP;
            size_t aoff = ((size_t)z*PP + (va ? gm : 0))*256 + k0;
            size_t boff = (size_t)(n0 + row)*256 + k0;
#pragma unroll
            for (int j = 0; j < 2; j++) {
                int koff = seg8 + j*32;
                uint32_t o = (uint32_t)(row*TSTRIDE + koff)*2;
                cp16(aTh + o, g_nodesTH + aoff + koff, va);
                if (pair) cp16(aTl + o, g_nodesTL + aoff + koff, va);
                cp16(bT + o, bS + boff + koff, true);
            }
        }
    };

    MAINLOOP(8, (t < 4))

#pragma unroll
    for (int mt = 0; mt < 4; mt++) {
        int m = m0 + wm*64 + mt*16 + (lane>>2);
#pragma unroll
        for (int nt = 0; nt < 4; nt++) {
            int n = n0 + wn*32 + nt*8 + (lane&3)*2;
            float bv0 = bias[n], bv1 = bias[n+1];
#pragma unroll
            for (int half = 0; half < 2; half++) {
                int mm = m + half*8;
                if (mm >= PP) continue;
                float v0 = acc[mt][nt][half*2+0] + bv0;
                float v1 = acc[mt][nt][half*2+1] + bv1;
                __half h0 = __float2half_rn(v0);
                __half h1 = __float2half_rn(v1);
                __half l0 = __float2half_rn(v0 - __half2float(h0));
                __half l1 = __float2half_rn(v1 - __half2float(h1));
                size_t o = ((size_t)z*PP + mm)*256 + n;
                *(__half2*)&g_thTH[o] = __halves2half2(h0, h1);
                *(__half2*)&g_thTL[o] = __halves2half2(l0, l1);
            }
        }
    }
}

// ============ softmax rows -> fp16 attention (hi only) ============
__device__ __forceinline__ float block_reduce(float v, bool is_max) {
    __shared__ float s[32];
    __syncthreads();
#pragma unroll
    for (int o = 16; o > 0; o >>= 1) {
        float t = __shfl_xor_sync(0xffffffffu, v, o);
        v = is_max ? fmaxf(v, t) : (v + t);
    }
    const int w = threadIdx.x >> 5, l = threadIdx.x & 31;
    if (l == 0) s[w] = v;
    __syncthreads();
    if (w == 0) {
        v = (l < 8) ? s[l] : (is_max ? -INFINITY : 0.f);
#pragma unroll
        for (int o = 4; o > 0; o >>= 1) {
            float t = __shfl_xor_sync(0xffffffffu, v, o);
            v = is_max ? fmaxf(v, t) : (v + t);
        }
        if (l == 0) s[0] = v;
    }
    __syncthreads();
    return s[0];
}

__global__ __launch_bounds__(256) void softmax_fp() {
    const size_t row = blockIdx.x;
    const float* srow = g_scores + row*PP;
    __half* hrow = g_atnH + row*PP;
    const int t = threadIdx.x;
    float v[7];
    float mx = -INFINITY;
#pragma unroll
    for (int i = 0; i < 7; i++) {
        int idx = t + i*256;
        v[i] = (idx < PP) ? srow[idx] : -INFINITY;
        mx = fmaxf(mx, v[i]);
    }
    mx = block_reduce(mx, true);
    float sum = 0.f;
#pragma unroll
    for (int i = 0; i < 7; i++) {
        int idx = t + i*256;
        if (idx < PP) { v[i] = __expf(v[i] - mx); sum += v[i]; }
    }
    sum = block_reduce(sum, false);
    const float inv = 1.f / sum;
#pragma unroll
    for (int i = 0; i < 7; i++) {
        int idx = t + i*256;
        if (idx < PP) hrow[idx] = __float2half_rn(v[i] * inv);
    }
}

// ============ split / transpose prep kernels ============
__device__ __forceinline__ void hsplit(float v, __half* h, __half* l) {
    __half hh = __float2half_rn(v);
    *h = hh;
    *l = __float2half_rn(v - __half2float(hh));
}

__global__ __launch_bounds__(256) void tsplit(const float* __restrict__ src,
                                              __half* __restrict__ dh,
                                              __half* __restrict__ dl) {
    __shared__ float tile[32][33];
    const int z = blockIdx.z, p0 = blockIdx.x*32, c0 = blockIdx.y*32;
    const int tx = threadIdx.x, ty = threadIdx.y;
    const float* s = src + (size_t)z*CP;
#pragma unroll
    for (int k = 0; k < 4; k++)
        tile[ty + 8*k][tx] = s[(size_t)(c0 + ty + 8*k)*PP + p0 + tx];
    __syncthreads();
#pragma unroll
    for (int k = 0; k < 4; k++) {
        float v = tile[tx][ty + 8*k];
        size_t o = ((size_t)z*PP + p0 + ty + 8*k)*256 + c0 + tx;
        hsplit(v, &dh[o], &dl[o]);
    }
}

__global__ __launch_bounds__(256) void aggT_t() {
    __shared__ float tile[32][33];
    const int z = blockIdx.z, p0 = blockIdx.x*32, c0 = blockIdx.y*32;
    const int n = z >> 2, b = z & 3;
    const int tx = threadIdx.x, ty = threadIdx.y;
    const float* m1 = g_msg + (size_t)(8*n + b)*CP;
    const float* m2 = g_msg + (size_t)(8*n + 4 + b)*CP;
#pragma unroll
    for (int k = 0; k < 4; k++) {
        size_t o = (size_t)(c0 + ty + 8*k)*PP + p0 + tx;
        tile[ty + 8*k][tx] = m1[o] + m2[o];
    }
    __syncthreads();
#pragma unroll
    for (int k = 0; k < 4; k++) {
        size_t o = ((size_t)z*PP + p0 + ty + 8*k)*256 + c0 + tx;
        g_aggTH[o] = __float2half_rn(tile[tx][ty + 8*k]);
    }
}

__global__ __launch_bounds__(256) void rhT_t() {
    __shared__ float tile[32][33];
    const int z = blockIdx.z, p0 = blockIdx.x*32, c0 = blockIdx.y*32;
    const int tx = threadIdx.x, ty = threadIdx.y;
    const float* gp = g_gates + (size_t)z*512*PP;
    const float* hp = g_nodes + (size_t)z*CP;
#pragma unroll
    for (int k = 0; k < 4; k++) {
        size_t o = (size_t)(c0 + ty + 8*k)*PP + p0 + tx;
        float g = gp[o];
        float r = 1.f / (1.f + __expf(-g));
        tile[ty + 8*k][tx] = r * hp[o];
    }
    __syncthreads();
#pragma unroll
    for (int k = 0; k < 4; k++) {
        size_t o = ((size_t)z*PP + p0 + ty + 8*k)*256 + c0 + tx;
        g_rhTH[o] = __float2half_rn(tile[tx][ty + 8*k]);
    }
}

// unordered pair sums, K-major [pair*b][c][q] (H only)
__global__ __launch_bounds__(256) void sum_split() {
    size_t i = (size_t)blockIdx.x*256 + threadIdx.x;
    if (i >= (size_t)NN*BCP) return;
    int z2 = (int)(i / CP); size_t cp = i % CP;
    int pr = z2 >> 2, b = z2 & 3;
    float v = g_nodes[(size_t)(c_p0[pr]*BB + b)*CP + cp] +
              g_nodes[(size_t)(c_p1[pr]*BB + b)*CP + cp];
    g_sumH[i] = __float2half_rn(v);
}

__global__ __launch_bounds__(256) void update_kernel() {
    size_t i = (size_t)blockIdx.x*256 + threadIdx.x;
    if (i >= (size_t)NBCP) return;
    size_t nb = i / CP, cp = i % CP;
    float gz = g_gates[nb*(size_t)(512*PP) + (size_t)CC*PP + cp];
    float zv = 1.f / (1.f + __expf(-gz));
    float h = g_nodes[i];
    float cd = tanhf(g_cand[i]);
    g_nodes[i] = (1.f - zv)*h + zv*cd;
}

// conv weights: w[oc][ci][3][3] -> [s][oc][ci] fp16 (H only)
__global__ __launch_bounds__(256) void wsplit_h(const float* __restrict__ w,
                                                __half* __restrict__ dh, int OC) {
    size_t i = (size_t)blockIdx.x*256 + threadIdx.x;
    size_t total = (size_t)9*OC*512;
    if (i >= total) return;
    int ci = (int)(i & 511);
    int oc = (int)((i >> 9) % OC);
    int s  = (int)(i / ((size_t)OC*512));
    dh[i] = __float2half_rn(w[((size_t)oc*512 + ci)*9 + s]);
}

__global__ __launch_bounds__(256) void wtheta_split(const float* __restrict__ w) {
    int i = blockIdx.x*256 + threadIdx.x;
    if (i >= CC*CC) return;
    hsplit(w[i], &g_wtH[i], &g_wtL[i]);
}

__global__ __launch_bounds__(256) void copy_in(const float* __restrict__ src) {
    size_t i = (size_t)blockIdx.x*256 + threadIdx.x;
    if (i < (size_t)NBCP/4) ((float4*)g_nodes)[i] = ((const float4*)src)[i];
}
__global__ __launch_bounds__(256) void copy_out(float* __restrict__ dst) {
    size_t i = (size_t)blockIdx.x*256 + threadIdx.x;
    if (i < (size_t)NBCP/4) ((float4*)dst)[i] = ((const float4*)g_nodes)[i];
}

// ---------------- host launch ----------------
extern "C" void kernel_launch(void* const* d_in, const int* in_sizes, int n_in,
                              void* d_out, int out_size) {
    const float* in_nodes = (const float*)d_in[0];
    const float* theta_w  = (const float*)d_in[1];
    const float* theta_b  = (const float*)d_in[2];
    const float* gw       = (const float*)d_in[3];
    const float* gb       = (const float*)d_in[4];
    const float* cw       = (const float*)d_in[5];
    const float* cb       = (const float*)d_in[6];
    float* out = (float*)d_out;

    __half *p_wgH, *p_wcH, *p_nTH, *p_nTL, *p_rhH;
    float *p_nodes, *p_gates, *p_cand;
    cudaGetSymbolAddress((void**)&p_wgH, g_wgH);
    cudaGetSymbolAddress((void**)&p_wcH, g_wcH);
    cudaGetSymbolAddress((void**)&p_nTH, g_nodesTH);
    cudaGetSymbolAddress((void**)&p_nTL, g_nodesTL);
    cudaGetSymbolAddress((void**)&p_rhH, g_rhTH);
    cudaGetSymbolAddress((void**)&p_nodes, g_nodes);
    cudaGetSymbolAddress((void**)&p_gates, g_gates);
    cudaGetSymbolAddress((void**)&p_cand,  g_cand);

    copy_in<<<(NBCP/4 + 255)/256, 256>>>(in_nodes);
    wsplit_h<<<((size_t)9*512*512 + 255)/256, 256>>>(gw, p_wgH, 512);
    wsplit_h<<<((size_t)9*256*512 + 255)/256, 256>>>(cw, p_wcH, 256);
    wtheta_split<<<(CC*CC + 255)/256, 256>>>(theta_w);

    const int EW = NBCP/256;  // 19200
    const dim3 tgrid(50, 8, 12), tblk(32, 8);
    for (int pass = 0; pass < 2; pass++) {
        tsplit<<<tgrid, tblk>>>(p_nodes, p_nTH, p_nTL);
        theta_mma<<<dim3(2, 13, NBB), 256>>>(theta_b);
        sum_split<<<EW, 256>>>();
        scores_mma<<<dim3(13, 13, EE*BB), 256>>>();
        softmax_fp<<<EE*BB*PP, 256>>>();
        msg_mma<<<dim3(13, 2, EE*BB), 256>>>();
        aggT_t<<<tgrid, tblk>>>();
        conv_mma<<<dim3(13, 4, NBB), 256>>>(p_wgH, gb, p_nTH, p_gates, 512);
        rhT_t<<<tgrid, tblk>>>();
        conv_mma<<<dim3(13, 2, NBB), 256>>>(p_wcH, cb, p_rhH, p_cand, 256);
        update_kernel<<<EW, 256>>>();
    }
    copy_out<<<(NBCP/4 + 255)/256, 256>>>(out);
}